// round 6
// baseline (speedup 1.0000x reference)
#include <cuda_runtime.h>
#include <cstdint>

#define SEQ   2048
#define BATCH 2
#define NH    16
#define DH    64
#define DM    1024
#define MTOT  (BATCH*SEQ)   // 4096 rows

// Scratch (device globals: no allocation allowed in kernel_launch)
__device__ float g_q[(size_t)MTOT * DM];
__device__ float g_k[(size_t)MTOT * DM];
__device__ float g_v[(size_t)MTOT * DM];
__device__ float g_z[(size_t)MTOT * DM];

// ===========================================================================
// mma.sync m16n8k8 tf32 + cp.async helpers
// ===========================================================================
__device__ __forceinline__ void mma_tf32(float* d, const unsigned* a, const unsigned* b) {
    asm volatile("mma.sync.aligned.m16n8k8.row.col.f32.tf32.tf32.f32 "
        "{%0,%1,%2,%3}, {%4,%5,%6,%7}, {%8,%9}, {%0,%1,%2,%3};"
        : "+f"(d[0]), "+f"(d[1]), "+f"(d[2]), "+f"(d[3])
        : "r"(a[0]), "r"(a[1]), "r"(a[2]), "r"(a[3]), "r"(b[0]), "r"(b[1]));
}

__device__ __forceinline__ unsigned f2tf32(float f) {
    unsigned r;
    asm("cvt.rna.tf32.f32 %0, %1;" : "=r"(r) : "f"(f));
    return r;
}

__device__ __forceinline__ unsigned smem_u32(const void* p) {
    unsigned r;
    asm("{ .reg .u64 t; cvta.to.shared.u64 t, %1; cvt.u32.u64 %0, t; }"
        : "=r"(r) : "l"(p));
    return r;
}

__device__ __forceinline__ void cp16(unsigned dst, const void* src) {
    asm volatile("cp.async.cg.shared.global [%0], [%1], 16;" :: "r"(dst), "l"(src));
}
#define CP_COMMIT()  asm volatile("cp.async.commit_group;" ::: "memory")
#define CP_WAIT(n)   asm volatile("cp.async.wait_group %0;" :: "n"(n) : "memory")

// convert 4 floats in place (smem) to tf32-rna bit patterns
__device__ __forceinline__ void cvt4_inplace(float* p) {
    float4 t = *(float4*)p;
    uint4 u = { f2tf32(t.x), f2tf32(t.y), f2tf32(t.z), f2tf32(t.w) };
    *(uint4*)p = u;
}

// ===========================================================================
// tf32 tensor GEMM, cp.async 2-stage pipeline + once-per-tile smem cvt:
//   C[4096,1024] = A[4096,1024] @ W + bias
//   MODE 0: B[k][n] = W[k*1024 + n]       MODE 1: W[(n>>6)*65536 + k*64 + (n&63)]
// Smem (floats): As[2] @ 0 / 4608 (128x36), Bs[2] @ 9216 / 13440 (32x132).
// ===========================================================================
#define BM 128
#define BN 128
#define KC 32
#define NCHUNK (DM / KC)   // 32
#define AST 36
#define BST 132
#define GEMM_SMEM 70656

template<int MODE>
__global__ __launch_bounds__(256, 2) void tc_gemm(
    const float* __restrict__ A, const float* __restrict__ W,
    const float* __restrict__ bias, float* __restrict__ C)
{
    extern __shared__ __align__(16) float smemf[];
    const unsigned sbase = smem_u32(smemf);

    const int tid = threadIdx.x;
    const int wid = tid >> 5, lane = tid & 31;
    const int g = lane >> 2, tig = lane & 3;
    const int warp_m = wid & 1, warp_n = wid >> 1;
    const int m0 = blockIdx.y * BM, n0 = blockIdx.x * BN;

    // load geometry
    const int ra = tid >> 1, ka = (tid & 1) * 16;
    const float* Aptr = A + (size_t)(m0 + ra) * DM + ka;
    const unsigned aDst = sbase + (ra * AST + ka) * 4;
    const int nb = lane * 4, kb = wid * 4;
    const int n_g = n0 + nb;
    const float* Bptr = (MODE == 1)
        ? W + (size_t)(n_g >> 6) * (DM * DH) + (n_g & 63)
        : W + n_g;
    const size_t bstride = (MODE == 1) ? DH : DM;
    const unsigned bDst = sbase + (9216 + kb * BST + nb) * 4;

    float acc[4][4][4];
    #pragma unroll
    for (int mt = 0; mt < 4; mt++)
        #pragma unroll
        for (int nt = 0; nt < 4; nt++)
            #pragma unroll
            for (int i = 0; i < 4; i++) acc[mt][nt][i] = 0.f;

    auto stage = [&](int c, int buf) {
        const float* ap = Aptr + c * KC;
        const unsigned ad = aDst + buf * (4608 * 4);
        #pragma unroll
        for (int f = 0; f < 4; f++) cp16(ad + f * 16, ap + f * 4);
        const unsigned bd = bDst + buf * (4224 * 4);
        #pragma unroll
        for (int j = 0; j < 4; j++)
            cp16(bd + j * (BST * 4), Bptr + (size_t)(c * KC + kb + j) * bstride);
    };

    stage(0, 0); CP_COMMIT();

    for (int c = 0; c < NCHUNK; c++) {
        if (c + 1 < NCHUNK) { stage(c + 1, (c + 1) & 1); CP_COMMIT(); CP_WAIT(1); }
        else                { CP_WAIT(0); }

        // convert own staged floats -> tf32 (own cp groups complete after wait)
        {
            float* ab = smemf + (c & 1) * 4608 + ra * AST + ka;
            #pragma unroll
            for (int f = 0; f < 4; f++) cvt4_inplace(ab + 4 * f);
            float* bb = smemf + 9216 + (c & 1) * 4224 + kb * BST + nb;
            #pragma unroll
            for (int j = 0; j < 4; j++) cvt4_inplace(bb + j * BST);
        }
        __syncthreads();

        const unsigned* Asb = (const unsigned*)(smemf + (c & 1) * 4608);
        const unsigned* Bsb = (const unsigned*)(smemf + 9216 + (c & 1) * 4224);
        #pragma unroll
        for (int kk = 0; kk < 4; kk++) {
            const int k0 = kk * 8;
            unsigned af[4][4], bf[4][2];
            #pragma unroll
            for (int mt = 0; mt < 4; mt++) {
                const int rb = warp_m * 64 + mt * 16 + g;
                af[mt][0] = Asb[rb * AST + k0 + tig];
                af[mt][1] = Asb[(rb + 8) * AST + k0 + tig];
                af[mt][2] = Asb[rb * AST + k0 + tig + 4];
                af[mt][3] = Asb[(rb + 8) * AST + k0 + tig + 4];
            }
            #pragma unroll
            for (int nt = 0; nt < 4; nt++) {
                const int cb = warp_n * 32 + nt * 8 + g;
                bf[nt][0] = Bsb[(k0 + tig) * BST + cb];
                bf[nt][1] = Bsb[(k0 + tig + 4) * BST + cb];
            }
            #pragma unroll
            for (int mt = 0; mt < 4; mt++)
                #pragma unroll
                for (int nt = 0; nt < 4; nt++)
                    mma_tf32(acc[mt][nt], af[mt], bf[nt]);
        }
        __syncthreads();
    }

    #pragma unroll
    for (int mt = 0; mt < 4; mt++) {
        const int r0 = m0 + warp_m * 64 + mt * 16 + g;
        #pragma unroll
        for (int nt = 0; nt < 4; nt++) {
            const int col = n0 + warp_n * 32 + nt * 8 + 2 * tig;
            const float bx = bias[col], by = bias[col + 1];
            float2 v0 = { acc[mt][nt][0] + bx, acc[mt][nt][1] + by };
            float2 v1 = { acc[mt][nt][2] + bx, acc[mt][nt][3] + by };
            *(float2*)&C[(size_t)r0 * DM + col] = v0;
            *(float2*)&C[(size_t)(r0 + 8) * DM + col] = v1;
        }
    }
}

// ===========================================================================
// Flash attention, mma.sync tf32 + cp.async 2-stage K/V pipeline +
// once-per-tile smem cvt. Block = 128 q rows x one (b,h). kv tiles of 64.
// Smem (floats): K[2] @ 0 / 4352 (64x68), V[2] @ 8704 / 13312 (64x72).
// ===========================================================================
#define KSTR 68
#define VSTR 72
#define FLASH_SMEM 71680

__global__ __launch_bounds__(256, 2) void flash_mma(
    const float* __restrict__ Q, const float* __restrict__ K,
    const float* __restrict__ V, float* __restrict__ Z)
{
    extern __shared__ __align__(16) float smemf[];
    const unsigned sbase = smem_u32(smemf);

    const int tid = threadIdx.x;
    const int wid = tid >> 5, lane = tid & 31;
    const int g = lane >> 2, tig = lane & 3;
    const int qt = gridDim.x - 1 - blockIdx.x;       // heavy tiles first
    const int bh = blockIdx.y;
    const int b = bh >> 4, h = bh & 15;
    const size_t base = ((size_t)b * SEQ * NH + h) * DH;
    const int qrow0 = qt * 128 + wid * 16;

    const int srow = tid >> 2;          // staging row 0..63
    const int sc16 = (tid & 3) * 16;    // staging col group (16 floats)

    // ---- Q -> register A-fragments (scale folded; stage via K buf0) ----
    unsigned aq[8][4];
    #pragma unroll
    for (int pass = 0; pass < 2; pass++) {
        const int qsrow = qt * 128 + pass * 64 + srow;
        #pragma unroll
        for (int i = 0; i < 4; i++) {
            float4 qv = *(const float4*)&Q[base + (size_t)qsrow * DM + sc16 + 4 * i];
            uint4 u = { f2tf32(qv.x * 0.125f), f2tf32(qv.y * 0.125f),
                        f2tf32(qv.z * 0.125f), f2tf32(qv.w * 0.125f) };
            *(uint4*)&smemf[srow * KSTR + sc16 + 4 * i] = u;
        }
        __syncthreads();
        if ((wid >> 2) == pass) {
            const unsigned* qs = (const unsigned*)smemf;
            const int r = (wid & 3) * 16 + g;
            #pragma unroll
            for (int kk = 0; kk < 8; kk++) {
                aq[kk][0] = qs[r * KSTR + kk * 8 + tig];
                aq[kk][1] = qs[(r + 8) * KSTR + kk * 8 + tig];
                aq[kk][2] = qs[r * KSTR + kk * 8 + tig + 4];
                aq[kk][3] = qs[(r + 8) * KSTR + kk * 8 + tig + 4];
            }
        }
        __syncthreads();
    }

    float m0 = -1e30f, m1 = -1e30f, l0 = 0.f, l1 = 0.f;
    float oacc[8][4];
    #pragma unroll
    for (int nt = 0; nt < 8; nt++)
        #pragma unroll
        for (int i = 0; i < 4; i++) oacc[nt][i] = 0.f;

    const unsigned s1 = (lane & 28) | (tig >> 1);
    const unsigned s2 = s1 + 2;
    const int NKT = 2 * qt + 2;

    const unsigned kDst = sbase + (srow * KSTR + sc16) * 4;
    const unsigned vDst = sbase + (8704 + srow * VSTR + sc16) * 4;

    auto stage = [&](int kt, int buf) {
        const int ktb = kt * 64;
        const float* kp = K + base + (size_t)(ktb + srow) * DM + sc16;
        const float* vp = V + base + (size_t)(ktb + srow) * DM + sc16;
        const unsigned kd = kDst + buf * (4352 * 4);
        const unsigned vd = vDst + buf * (4608 * 4);
        #pragma unroll
        for (int f = 0; f < 4; f++) { cp16(kd + f * 16, kp + f * 4); cp16(vd + f * 16, vp + f * 4); }
    };

    stage(0, 0); CP_COMMIT();

    for (int kt = 0; kt < NKT; kt++) {
        if (kt + 1 < NKT) { stage(kt + 1, (kt + 1) & 1); CP_COMMIT(); CP_WAIT(1); }
        else              { CP_WAIT(0); }

        // convert own staged K/V floats -> tf32 in place
        {
            float* kb = smemf + (kt & 1) * 4352 + srow * KSTR + sc16;
            float* vb = smemf + 8704 + (kt & 1) * 4608 + srow * VSTR + sc16;
            #pragma unroll
            for (int f = 0; f < 4; f++) { cvt4_inplace(kb + 4 * f); cvt4_inplace(vb + 4 * f); }
        }
        __syncthreads();

        const int ktb = kt * 64;
        if (ktb <= qrow0 + 15) {
            const unsigned* kbuf = (const unsigned*)(smemf + (kt & 1) * 4352);
            const unsigned* vbuf = (const unsigned*)(smemf + 8704 + (kt & 1) * 4608);

            // ---- S = Q K^T ----
            float sacc[8][4];
            #pragma unroll
            for (int nt = 0; nt < 8; nt++)
                #pragma unroll
                for (int i = 0; i < 4; i++) sacc[nt][i] = 0.f;

            #pragma unroll
            for (int kk = 0; kk < 8; kk++) {
                unsigned bf[8][2];
                #pragma unroll
                for (int nt = 0; nt < 8; nt++) {
                    bf[nt][0] = kbuf[(nt * 8 + g) * KSTR + kk * 8 + tig];
                    bf[nt][1] = kbuf[(nt * 8 + g) * KSTR + kk * 8 + tig + 4];
                }
                #pragma unroll
                for (int nt = 0; nt < 8; nt++)
                    mma_tf32(sacc[nt], aq[kk], bf[nt]);
            }

            // ---- causal mask (diagonal tiles only) ----
            if (ktb + 63 > qrow0) {
                #pragma unroll
                for (int nt = 0; nt < 8; nt++) {
                    const int kv0 = ktb + nt * 8 + 2 * tig;
                    if (kv0     > qrow0 + g)     sacc[nt][0] = -1e30f;
                    if (kv0 + 1 > qrow0 + g)     sacc[nt][1] = -1e30f;
                    if (kv0     > qrow0 + g + 8) sacc[nt][2] = -1e30f;
                    if (kv0 + 1 > qrow0 + g + 8) sacc[nt][3] = -1e30f;
                }
            }

            // ---- online softmax ----
            float rm0 = -1e30f, rm1 = -1e30f;
            #pragma unroll
            for (int nt = 0; nt < 8; nt++) {
                rm0 = fmaxf(rm0, fmaxf(sacc[nt][0], sacc[nt][1]));
                rm1 = fmaxf(rm1, fmaxf(sacc[nt][2], sacc[nt][3]));
            }
            rm0 = fmaxf(rm0, __shfl_xor_sync(0xffffffffu, rm0, 1));
            rm0 = fmaxf(rm0, __shfl_xor_sync(0xffffffffu, rm0, 2));
            rm1 = fmaxf(rm1, __shfl_xor_sync(0xffffffffu, rm1, 1));
            rm1 = fmaxf(rm1, __shfl_xor_sync(0xffffffffu, rm1, 2));
            const float mn0 = fmaxf(m0, rm0), mn1 = fmaxf(m1, rm1);
            const float al0 = __expf(m0 - mn0), al1 = __expf(m1 - mn1);
            float rs0 = 0.f, rs1 = 0.f;
            #pragma unroll
            for (int nt = 0; nt < 8; nt++) {
                sacc[nt][0] = __expf(sacc[nt][0] - mn0); rs0 += sacc[nt][0];
                sacc[nt][1] = __expf(sacc[nt][1] - mn0); rs0 += sacc[nt][1];
                sacc[nt][2] = __expf(sacc[nt][2] - mn1); rs1 += sacc[nt][2];
                sacc[nt][3] = __expf(sacc[nt][3] - mn1); rs1 += sacc[nt][3];
            }
            rs0 += __shfl_xor_sync(0xffffffffu, rs0, 1);
            rs0 += __shfl_xor_sync(0xffffffffu, rs0, 2);
            rs1 += __shfl_xor_sync(0xffffffffu, rs1, 1);
            rs1 += __shfl_xor_sync(0xffffffffu, rs1, 2);
            l0 = l0 * al0 + rs0;  l1 = l1 * al1 + rs1;
            m0 = mn0;             m1 = mn1;
            #pragma unroll
            for (int nt = 0; nt < 8; nt++) {
                oacc[nt][0] *= al0; oacc[nt][1] *= al0;
                oacc[nt][2] *= al1; oacc[nt][3] *= al1;
            }

            // ---- O += P V  (P fragment via shfl; V natural [kv][d]) ----
            #pragma unroll
            for (int kk = 0; kk < 8; kk++) {
                const float c0a = __shfl_sync(0xffffffffu, sacc[kk][0], s1);
                const float c1a = __shfl_sync(0xffffffffu, sacc[kk][1], s1);
                const float c2a = __shfl_sync(0xffffffffu, sacc[kk][2], s1);
                const float c3a = __shfl_sync(0xffffffffu, sacc[kk][3], s1);
                const float c0b = __shfl_sync(0xffffffffu, sacc[kk][0], s2);
                const float c1b = __shfl_sync(0xffffffffu, sacc[kk][1], s2);
                const float c2b = __shfl_sync(0xffffffffu, sacc[kk][2], s2);
                const float c3b = __shfl_sync(0xffffffffu, sacc[kk][3], s2);
                unsigned ap[4];
                ap[0] = f2tf32((tig & 1) ? c1a : c0a);
                ap[1] = f2tf32((tig & 1) ? c3a : c2a);
                ap[2] = f2tf32((tig & 1) ? c1b : c0b);
                ap[3] = f2tf32((tig & 1) ? c3b : c2b);
                unsigned bf[8][2];
                #pragma unroll
                for (int nt = 0; nt < 8; nt++) {
                    bf[nt][0] = vbuf[(kk * 8 + tig) * VSTR + nt * 8 + g];
                    bf[nt][1] = vbuf[(kk * 8 + tig + 4) * VSTR + nt * 8 + g];
                }
                #pragma unroll
                for (int nt = 0; nt < 8; nt++)
                    mma_tf32(oacc[nt], ap, bf[nt]);
            }
        }
        __syncthreads();
    }

    // ---- normalize + write z[b, s, h, d] ----
    const float i0 = 1.f / l0, i1 = 1.f / l1;
    #pragma unroll
    for (int nt = 0; nt < 8; nt++) {
        const int col = nt * 8 + 2 * tig;
        const int row = qrow0 + g;
        float2 v0 = { oacc[nt][0] * i0, oacc[nt][1] * i0 };
        float2 v1 = { oacc[nt][2] * i1, oacc[nt][3] * i1 };
        *(float2*)&Z[base + (size_t)row * DM + col] = v0;
        *(float2*)&Z[base + (size_t)(row + 8) * DM + col] = v1;
    }
}

// ---------------------------------------------------------------------------

extern "C" void kernel_launch(void* const* d_in, const int* in_sizes, int n_in,
                              void* d_out, int out_size)
{
    const float* x  = (const float*)d_in[0];
    const float* WQ = (const float*)d_in[1];
    const float* WK = (const float*)d_in[2];
    const float* WV = (const float*)d_in[3];
    const float* WO = (const float*)d_in[4];
    const float* bQ = (const float*)d_in[5];
    const float* bK = (const float*)d_in[6];
    const float* bV = (const float*)d_in[7];
    const float* bO = (const float*)d_in[8];
    float* out = (float*)d_out;

    float *q, *k, *v, *z;
    cudaGetSymbolAddress((void**)&q, g_q);
    cudaGetSymbolAddress((void**)&k, g_k);
    cudaGetSymbolAddress((void**)&v, g_v);
    cudaGetSymbolAddress((void**)&z, g_z);

    cudaFuncSetAttribute(tc_gemm<0>, cudaFuncAttributeMaxDynamicSharedMemorySize, GEMM_SMEM);
    cudaFuncSetAttribute(tc_gemm<1>, cudaFuncAttributeMaxDynamicSharedMemorySize, GEMM_SMEM);
    cudaFuncSetAttribute(flash_mma,  cudaFuncAttributeMaxDynamicSharedMemorySize, FLASH_SMEM);

    dim3 gg(DM / BN, MTOT / BM);        // (8, 32)
    tc_gemm<1><<<gg, 256, GEMM_SMEM>>>(x, WQ, bQ, q);
    tc_gemm<1><<<gg, 256, GEMM_SMEM>>>(x, WK, bK, k);
    tc_gemm<1><<<gg, 256, GEMM_SMEM>>>(x, WV, bV, v);
    flash_mma<<<dim3(SEQ / 128, BATCH * NH), 256, FLASH_SMEM>>>(q, k, v, z);
    tc_gemm<0><<<gg, 256, GEMM_SMEM>>>(z, WO, bO, out);
}

// round 7
// speedup vs baseline: 1.1182x; 1.1182x over previous
#include <cuda_runtime.h>
#include <cstdint>

#define SEQ   2048
#define BATCH 2
#define NH    16
#define DH    64
#define DM    1024
#define MTOT  (BATCH*SEQ)   // 4096 rows

// Scratch (device globals: no allocation allowed in kernel_launch)
__device__ float g_q[(size_t)MTOT * DM];
__device__ float g_k[(size_t)MTOT * DM];
__device__ float g_v[(size_t)MTOT * DM];
__device__ float g_z[(size_t)MTOT * DM];

// ===========================================================================
// mma.sync m16n8k8 tf32 + cp.async helpers
// ===========================================================================
__device__ __forceinline__ void mma_tf32(float* d, const unsigned* a, const unsigned* b) {
    asm volatile("mma.sync.aligned.m16n8k8.row.col.f32.tf32.tf32.f32 "
        "{%0,%1,%2,%3}, {%4,%5,%6,%7}, {%8,%9}, {%0,%1,%2,%3};"
        : "+f"(d[0]), "+f"(d[1]), "+f"(d[2]), "+f"(d[3])
        : "r"(a[0]), "r"(a[1]), "r"(a[2]), "r"(a[3]), "r"(b[0]), "r"(b[1]));
}

__device__ __forceinline__ unsigned f2tf32(float f) {
    unsigned r;
    asm("cvt.rna.tf32.f32 %0, %1;" : "=r"(r) : "f"(f));
    return r;
}

__device__ __forceinline__ unsigned smem_u32(const void* p) {
    unsigned r;
    asm("{ .reg .u64 t; cvta.to.shared.u64 t, %1; cvt.u32.u64 %0, t; }"
        : "=r"(r) : "l"(p));
    return r;
}

__device__ __forceinline__ void cp16(unsigned dst, const void* src) {
    asm volatile("cp.async.cg.shared.global [%0], [%1], 16;" :: "r"(dst), "l"(src));
}
#define CP_COMMIT()  asm volatile("cp.async.commit_group;" ::: "memory")
#define CP_WAIT(n)   asm volatile("cp.async.wait_group %0;" :: "n"(n) : "memory")

// ===========================================================================
// tf32 tensor GEMM, cp.async 3-stage pipeline, cvt at fragment read:
//   C[4096,1024] = A[4096,1024] @ W + bias
//   MODE 0: B[k][n] = W[k*1024 + n]       MODE 1: W[(n>>6)*65536 + k*64 + (n&63)]
// Smem (floats): As[3] @ 0/4608/9216 (128x36), Bs[3] @ 13824/18048/22272 (32x132).
// Total 26496 floats = 105984 B dynamic per CTA (2 CTAs/SM = 207 KB).
// ===========================================================================
#define BM 128
#define BN 128
#define KC 32
#define NCHUNK (DM / KC)   // 32
#define AST 36
#define BST 132
#define AOFF 4608
#define BBASE 13824
#define BOFF 4224
#define GEMM_SMEM 105984

template<int MODE>
__global__ __launch_bounds__(256, 2) void tc_gemm(
    const float* __restrict__ A, const float* __restrict__ W,
    const float* __restrict__ bias, float* __restrict__ C)
{
    extern __shared__ __align__(16) float smemf[];
    const unsigned sbase = smem_u32(smemf);

    const int tid = threadIdx.x;
    const int wid = tid >> 5, lane = tid & 31;
    const int g = lane >> 2, tig = lane & 3;
    const int warp_m = wid & 1, warp_n = wid >> 1;
    const int m0 = blockIdx.y * BM, n0 = blockIdx.x * BN;

    // load geometry
    const int ra = tid >> 1, ka = (tid & 1) * 16;
    const float* Aptr = A + (size_t)(m0 + ra) * DM + ka;
    const unsigned aDst = sbase + (ra * AST + ka) * 4;
    const int nb = lane * 4, kb = wid * 4;
    const int n_g = n0 + nb;
    const float* Bptr = (MODE == 1)
        ? W + (size_t)(n_g >> 6) * (DM * DH) + (n_g & 63)
        : W + n_g;
    const size_t bstride = (MODE == 1) ? DH : DM;
    const unsigned bDst = sbase + (BBASE + kb * BST + nb) * 4;

    float acc[4][4][4];
    #pragma unroll
    for (int mt = 0; mt < 4; mt++)
        #pragma unroll
        for (int nt = 0; nt < 4; nt++)
            #pragma unroll
            for (int i = 0; i < 4; i++) acc[mt][nt][i] = 0.f;

    auto stage = [&](int c, int buf) {
        const float* ap = Aptr + c * KC;
        const unsigned ad = aDst + buf * (AOFF * 4);
        #pragma unroll
        for (int f = 0; f < 4; f++) cp16(ad + f * 16, ap + f * 4);
        const unsigned bd = bDst + buf * (BOFF * 4);
        #pragma unroll
        for (int j = 0; j < 4; j++)
            cp16(bd + j * (BST * 4), Bptr + (size_t)(c * KC + kb + j) * bstride);
    };

    stage(0, 0); CP_COMMIT();
    stage(1, 1); CP_COMMIT();

    int buf = 0;
    for (int c = 0; c < NCHUNK; c++) {
        if (c + 2 < NCHUNK) { stage(c + 2, (c + 2) % 3); CP_COMMIT(); CP_WAIT(2); }
        else if (c + 1 < NCHUNK) { CP_WAIT(1); }
        else { CP_WAIT(0); }
        __syncthreads();

        const float* Asb = smemf + buf * AOFF;
        const float* Bsb = smemf + BBASE + buf * BOFF;
        #pragma unroll
        for (int kk = 0; kk < 4; kk++) {
            const int k0 = kk * 8;
            unsigned af[4][4], bf[4][2];
            #pragma unroll
            for (int mt = 0; mt < 4; mt++) {
                const int rb = warp_m * 64 + mt * 16 + g;
                af[mt][0] = f2tf32(Asb[rb * AST + k0 + tig]);
                af[mt][1] = f2tf32(Asb[(rb + 8) * AST + k0 + tig]);
                af[mt][2] = f2tf32(Asb[rb * AST + k0 + tig + 4]);
                af[mt][3] = f2tf32(Asb[(rb + 8) * AST + k0 + tig + 4]);
            }
            #pragma unroll
            for (int nt = 0; nt < 4; nt++) {
                const int cb = warp_n * 32 + nt * 8 + g;
                bf[nt][0] = f2tf32(Bsb[(k0 + tig) * BST + cb]);
                bf[nt][1] = f2tf32(Bsb[(k0 + tig + 4) * BST + cb]);
            }
            #pragma unroll
            for (int mt = 0; mt < 4; mt++)
                #pragma unroll
                for (int nt = 0; nt < 4; nt++)
                    mma_tf32(acc[mt][nt], af[mt], bf[nt]);
        }
        __syncthreads();
        buf = (buf == 2) ? 0 : buf + 1;
    }

    #pragma unroll
    for (int mt = 0; mt < 4; mt++) {
        const int r0 = m0 + warp_m * 64 + mt * 16 + g;
        #pragma unroll
        for (int nt = 0; nt < 4; nt++) {
            const int col = n0 + warp_n * 32 + nt * 8 + 2 * tig;
            const float bx = bias[col], by = bias[col + 1];
            float2 v0 = { acc[mt][nt][0] + bx, acc[mt][nt][1] + by };
            float2 v1 = { acc[mt][nt][2] + bx, acc[mt][nt][3] + by };
            *(float2*)&C[(size_t)r0 * DM + col] = v0;
            *(float2*)&C[(size_t)(r0 + 8) * DM + col] = v1;
        }
    }
}

// ===========================================================================
// Flash attention with mma.sync tf32 (R4 version — best measured).
// Block = 128 q rows x one (b,h). 8 warps, 16 q rows each. kv tiles of 64.
// Q in register A-fragments (scale 1/8 folded). K smem [kv][d] str 68,
// V smem transposed [d][kv] str 68. P stays in registers via shfl.
// ===========================================================================
#define KST 68   // smem row stride (floats) for K/V tiles

__global__ __launch_bounds__(256) void flash_mma(
    const float* __restrict__ Q, const float* __restrict__ K,
    const float* __restrict__ V, float* __restrict__ Z)
{
    __shared__ __align__(16) unsigned ks[64 * KST];
    __shared__ __align__(16) unsigned vs[64 * KST];

    const int tid = threadIdx.x;
    const int wid = tid >> 5, lane = tid & 31;
    const int g = lane >> 2, tig = lane & 3;
    const int qt = gridDim.x - 1 - blockIdx.x;       // heavy tiles first
    const int bh = blockIdx.y;
    const int b = bh >> 4, h = bh & 15;
    const size_t base = ((size_t)b * SEQ * NH + h) * DH;
    const int qrow0 = qt * 128 + wid * 16;

    const int lkv = tid >> 2;          // staging row 0..63
    const int ld0 = (tid & 3) * 16;    // staging col group

    // ---- Q -> register A-fragments (two passes through ks) ----
    unsigned aq[8][4];
    #pragma unroll
    for (int pass = 0; pass < 2; pass++) {
        const int srow = qt * 128 + pass * 64 + lkv;
        #pragma unroll
        for (int i = 0; i < 4; i++) {
            float4 qv = *(const float4*)&Q[base + (size_t)srow * DM + ld0 + 4 * i];
            uint4 u = { f2tf32(qv.x * 0.125f), f2tf32(qv.y * 0.125f),
                        f2tf32(qv.z * 0.125f), f2tf32(qv.w * 0.125f) };
            *(uint4*)&ks[lkv * KST + ld0 + 4 * i] = u;
        }
        __syncthreads();
        if ((wid >> 2) == pass) {
            const int r = (wid & 3) * 16 + g;
            #pragma unroll
            for (int kk = 0; kk < 8; kk++) {
                aq[kk][0] = ks[r * KST + kk * 8 + tig];
                aq[kk][1] = ks[(r + 8) * KST + kk * 8 + tig];
                aq[kk][2] = ks[r * KST + kk * 8 + tig + 4];
                aq[kk][3] = ks[(r + 8) * KST + kk * 8 + tig + 4];
            }
        }
        __syncthreads();
    }

    float m0 = -1e30f, m1 = -1e30f, l0 = 0.f, l1 = 0.f;
    float oacc[8][4];
    #pragma unroll
    for (int nt = 0; nt < 8; nt++)
        #pragma unroll
        for (int i = 0; i < 4; i++) oacc[nt][i] = 0.f;

    const int vkv = tid & 63;          // V staging: column-load for transpose
    const int vd0 = (tid >> 6) * 16;
    const unsigned s1 = (lane & 28) | (tig >> 1);
    const unsigned s2 = s1 + 2;
    const int NKT = 2 * qt + 2;

    for (int kt = 0; kt < NKT; kt++) {
        const int ktb = kt * 64;
        __syncthreads();
        // K tile [kv][d]
        #pragma unroll
        for (int i = 0; i < 4; i++) {
            float4 kv4 = *(const float4*)&K[base + (size_t)(ktb + lkv) * DM + ld0 + 4 * i];
            uint4 u = { f2tf32(kv4.x), f2tf32(kv4.y), f2tf32(kv4.z), f2tf32(kv4.w) };
            *(uint4*)&ks[lkv * KST + ld0 + 4 * i] = u;
        }
        // V tile transposed -> [d][kv]
        #pragma unroll
        for (int i = 0; i < 4; i++) {
            float4 vv = *(const float4*)&V[base + (size_t)(ktb + vkv) * DM + vd0 + 4 * i];
            vs[(vd0 + 4 * i + 0) * KST + vkv] = f2tf32(vv.x);
            vs[(vd0 + 4 * i + 1) * KST + vkv] = f2tf32(vv.y);
            vs[(vd0 + 4 * i + 2) * KST + vkv] = f2tf32(vv.z);
            vs[(vd0 + 4 * i + 3) * KST + vkv] = f2tf32(vv.w);
        }
        __syncthreads();

        if (ktb > qrow0 + 15) continue;   // tile fully masked for this warp

        // ---- S = Q K^T ----
        float sacc[8][4];
        #pragma unroll
        for (int nt = 0; nt < 8; nt++)
            #pragma unroll
            for (int i = 0; i < 4; i++) sacc[nt][i] = 0.f;

        #pragma unroll
        for (int kk = 0; kk < 8; kk++) {
            unsigned bf[8][2];
            #pragma unroll
            for (int nt = 0; nt < 8; nt++) {
                bf[nt][0] = ks[(nt * 8 + g) * KST + kk * 8 + tig];
                bf[nt][1] = ks[(nt * 8 + g) * KST + kk * 8 + tig + 4];
            }
            #pragma unroll
            for (int nt = 0; nt < 8; nt++)
                mma_tf32(sacc[nt], aq[kk], bf[nt]);
        }

        // ---- causal mask (diagonal tiles only) ----
        if (ktb + 63 > qrow0) {
            #pragma unroll
            for (int nt = 0; nt < 8; nt++) {
                const int kv0 = ktb + nt * 8 + 2 * tig;
                if (kv0     > qrow0 + g)     sacc[nt][0] = -1e30f;
                if (kv0 + 1 > qrow0 + g)     sacc[nt][1] = -1e30f;
                if (kv0     > qrow0 + g + 8) sacc[nt][2] = -1e30f;
                if (kv0 + 1 > qrow0 + g + 8) sacc[nt][3] = -1e30f;
            }
        }

        // ---- online softmax ----
        float rm0 = -1e30f, rm1 = -1e30f;
        #pragma unroll
        for (int nt = 0; nt < 8; nt++) {
            rm0 = fmaxf(rm0, fmaxf(sacc[nt][0], sacc[nt][1]));
            rm1 = fmaxf(rm1, fmaxf(sacc[nt][2], sacc[nt][3]));
        }
        rm0 = fmaxf(rm0, __shfl_xor_sync(0xffffffffu, rm0, 1));
        rm0 = fmaxf(rm0, __shfl_xor_sync(0xffffffffu, rm0, 2));
        rm1 = fmaxf(rm1, __shfl_xor_sync(0xffffffffu, rm1, 1));
        rm1 = fmaxf(rm1, __shfl_xor_sync(0xffffffffu, rm1, 2));
        const float mn0 = fmaxf(m0, rm0), mn1 = fmaxf(m1, rm1);
        const float al0 = __expf(m0 - mn0), al1 = __expf(m1 - mn1);
        float rs0 = 0.f, rs1 = 0.f;
        #pragma unroll
        for (int nt = 0; nt < 8; nt++) {
            sacc[nt][0] = __expf(sacc[nt][0] - mn0); rs0 += sacc[nt][0];
            sacc[nt][1] = __expf(sacc[nt][1] - mn0); rs0 += sacc[nt][1];
            sacc[nt][2] = __expf(sacc[nt][2] - mn1); rs1 += sacc[nt][2];
            sacc[nt][3] = __expf(sacc[nt][3] - mn1); rs1 += sacc[nt][3];
        }
        rs0 += __shfl_xor_sync(0xffffffffu, rs0, 1);
        rs0 += __shfl_xor_sync(0xffffffffu, rs0, 2);
        rs1 += __shfl_xor_sync(0xffffffffu, rs1, 1);
        rs1 += __shfl_xor_sync(0xffffffffu, rs1, 2);
        l0 = l0 * al0 + rs0;  l1 = l1 * al1 + rs1;
        m0 = mn0;             m1 = mn1;
        #pragma unroll
        for (int nt = 0; nt < 8; nt++) {
            oacc[nt][0] *= al0; oacc[nt][1] *= al0;
            oacc[nt][2] *= al1; oacc[nt][3] *= al1;
        }

        // ---- O += P V  (P fragment via shfl from S fragment) ----
        #pragma unroll
        for (int kk = 0; kk < 8; kk++) {
            const float c0a = __shfl_sync(0xffffffffu, sacc[kk][0], s1);
            const float c1a = __shfl_sync(0xffffffffu, sacc[kk][1], s1);
            const float c2a = __shfl_sync(0xffffffffu, sacc[kk][2], s1);
            const float c3a = __shfl_sync(0xffffffffu, sacc[kk][3], s1);
            const float c0b = __shfl_sync(0xffffffffu, sacc[kk][0], s2);
            const float c1b = __shfl_sync(0xffffffffu, sacc[kk][1], s2);
            const float c2b = __shfl_sync(0xffffffffu, sacc[kk][2], s2);
            const float c3b = __shfl_sync(0xffffffffu, sacc[kk][3], s2);
            unsigned ap[4];
            ap[0] = f2tf32((tig & 1) ? c1a : c0a);
            ap[1] = f2tf32((tig & 1) ? c3a : c2a);
            ap[2] = f2tf32((tig & 1) ? c1b : c0b);
            ap[3] = f2tf32((tig & 1) ? c3b : c2b);
            unsigned bf[8][2];
            #pragma unroll
            for (int nt = 0; nt < 8; nt++) {
                bf[nt][0] = vs[(nt * 8 + g) * KST + kk * 8 + tig];
                bf[nt][1] = vs[(nt * 8 + g) * KST + kk * 8 + tig + 4];
            }
            #pragma unroll
            for (int nt = 0; nt < 8; nt++)
                mma_tf32(oacc[nt], ap, bf[nt]);
        }
    }

    // ---- normalize + write z[b, s, h, d] ----
    const float i0 = 1.f / l0, i1 = 1.f / l1;
    #pragma unroll
    for (int nt = 0; nt < 8; nt++) {
        const int col = nt * 8 + 2 * tig;
        const int row = qrow0 + g;
        float2 v0 = { oacc[nt][0] * i0, oacc[nt][1] * i0 };
        float2 v1 = { oacc[nt][2] * i1, oacc[nt][3] * i1 };
        *(float2*)&Z[base + (size_t)row * DM + col] = v0;
        *(float2*)&Z[base + (size_t)(row + 8) * DM + col] = v1;
    }
}

// ---------------------------------------------------------------------------

extern "C" void kernel_launch(void* const* d_in, const int* in_sizes, int n_in,
                              void* d_out, int out_size)
{
    const float* x  = (const float*)d_in[0];
    const float* WQ = (const float*)d_in[1];
    const float* WK = (const float*)d_in[2];
    const float* WV = (const float*)d_in[3];
    const float* WO = (const float*)d_in[4];
    const float* bQ = (const float*)d_in[5];
    const float* bK = (const float*)d_in[6];
    const float* bV = (const float*)d_in[7];
    const float* bO = (const float*)d_in[8];
    float* out = (float*)d_out;

    float *q, *k, *v, *z;
    cudaGetSymbolAddress((void**)&q, g_q);
    cudaGetSymbolAddress((void**)&k, g_k);
    cudaGetSymbolAddress((void**)&v, g_v);
    cudaGetSymbolAddress((void**)&z, g_z);

    cudaFuncSetAttribute(tc_gemm<0>, cudaFuncAttributeMaxDynamicSharedMemorySize, GEMM_SMEM);
    cudaFuncSetAttribute(tc_gemm<1>, cudaFuncAttributeMaxDynamicSharedMemorySize, GEMM_SMEM);

    dim3 gg(DM / BN, MTOT / BM);        // (8, 32)
    tc_gemm<1><<<gg, 256, GEMM_SMEM>>>(x, WQ, bQ, q);
    tc_gemm<1><<<gg, 256, GEMM_SMEM>>>(x, WK, bK, k);
    tc_gemm<1><<<gg, 256, GEMM_SMEM>>>(x, WV, bV, v);
    flash_mma<<<dim3(SEQ / 128, BATCH * NH), 256>>>(q, k, v, z);
    tc_gemm<0><<<gg, 256, GEMM_SMEM>>>(z, WO, bO, out);
}

// round 8
// speedup vs baseline: 1.3078x; 1.1695x over previous
#include <cuda_runtime.h>
#include <cuda_fp16.h>
#include <cstdint>

#define SEQ   2048
#define BATCH 2
#define NH    16
#define DH    64
#define DM    1024
#define MTOT  (BATCH*SEQ)   // 4096 rows

// Scratch (device globals: no allocation allowed in kernel_launch)
__device__ float g_q[(size_t)MTOT * DM];
__device__ float g_k[(size_t)MTOT * DM];
__device__ float g_v[(size_t)MTOT * DM];
__device__ float g_z[(size_t)MTOT * DM];

// ===========================================================================
// mma.sync helpers
// ===========================================================================
__device__ __forceinline__ void mma_tf32(float* d, const unsigned* a, const unsigned* b) {
    asm volatile("mma.sync.aligned.m16n8k8.row.col.f32.tf32.tf32.f32 "
        "{%0,%1,%2,%3}, {%4,%5,%6,%7}, {%8,%9}, {%0,%1,%2,%3};"
        : "+f"(d[0]), "+f"(d[1]), "+f"(d[2]), "+f"(d[3])
        : "r"(a[0]), "r"(a[1]), "r"(a[2]), "r"(a[3]), "r"(b[0]), "r"(b[1]));
}

__device__ __forceinline__ void mma_f16(float* d, const unsigned* a, const unsigned* b) {
    asm volatile("mma.sync.aligned.m16n8k16.row.col.f32.f16.f16.f32 "
        "{%0,%1,%2,%3}, {%4,%5,%6,%7}, {%8,%9}, {%0,%1,%2,%3};"
        : "+f"(d[0]), "+f"(d[1]), "+f"(d[2]), "+f"(d[3])
        : "r"(a[0]), "r"(a[1]), "r"(a[2]), "r"(a[3]), "r"(b[0]), "r"(b[1]));
}

__device__ __forceinline__ unsigned f2tf32(float f) {
    unsigned r;
    asm("cvt.rna.tf32.f32 %0, %1;" : "=r"(r) : "f"(f));
    return r;
}

// pack two floats -> half2 {lo, hi}
__device__ __forceinline__ unsigned pack_h2(float lo, float hi) {
    unsigned r;
    asm("cvt.rn.f16x2.f32 %0, %1, %2;" : "=r"(r) : "f"(hi), "f"(lo));
    return r;
}

__device__ __forceinline__ unsigned smem_u32(const void* p) {
    unsigned r;
    asm("{ .reg .u64 t; cvta.to.shared.u64 t, %1; cvt.u32.u64 %0, t; }"
        : "=r"(r) : "l"(p));
    return r;
}

__device__ __forceinline__ void cp16(unsigned dst, const void* src) {
    asm volatile("cp.async.cg.shared.global [%0], [%1], 16;" :: "r"(dst), "l"(src));
}
#define CP_COMMIT()  asm volatile("cp.async.commit_group;" ::: "memory")
#define CP_WAIT(n)   asm volatile("cp.async.wait_group %0;" :: "n"(n) : "memory")

// ===========================================================================
// tf32 tensor GEMM, cp.async 3-stage pipeline (unchanged from R7)
// ===========================================================================
#define BM 128
#define BN 128
#define KC 32
#define NCHUNK (DM / KC)   // 32
#define AST 36
#define BST 132
#define AOFF 4608
#define BBASE 13824
#define BOFF 4224
#define GEMM_SMEM 105984

template<int MODE>
__global__ __launch_bounds__(256, 2) void tc_gemm(
    const float* __restrict__ A, const float* __restrict__ W,
    const float* __restrict__ bias, float* __restrict__ C)
{
    extern __shared__ __align__(16) float smemf[];
    const unsigned sbase = smem_u32(smemf);

    const int tid = threadIdx.x;
    const int wid = tid >> 5, lane = tid & 31;
    const int g = lane >> 2, tig = lane & 3;
    const int warp_m = wid & 1, warp_n = wid >> 1;
    const int m0 = blockIdx.y * BM, n0 = blockIdx.x * BN;

    const int ra = tid >> 1, ka = (tid & 1) * 16;
    const float* Aptr = A + (size_t)(m0 + ra) * DM + ka;
    const unsigned aDst = sbase + (ra * AST + ka) * 4;
    const int nb = lane * 4, kb = wid * 4;
    const int n_g = n0 + nb;
    const float* Bptr = (MODE == 1)
        ? W + (size_t)(n_g >> 6) * (DM * DH) + (n_g & 63)
        : W + n_g;
    const size_t bstride = (MODE == 1) ? DH : DM;
    const unsigned bDst = sbase + (BBASE + kb * BST + nb) * 4;

    float acc[4][4][4];
    #pragma unroll
    for (int mt = 0; mt < 4; mt++)
        #pragma unroll
        for (int nt = 0; nt < 4; nt++)
            #pragma unroll
            for (int i = 0; i < 4; i++) acc[mt][nt][i] = 0.f;

    auto stage = [&](int c, int buf) {
        const float* ap = Aptr + c * KC;
        const unsigned ad = aDst + buf * (AOFF * 4);
        #pragma unroll
        for (int f = 0; f < 4; f++) cp16(ad + f * 16, ap + f * 4);
        const unsigned bd = bDst + buf * (BOFF * 4);
        #pragma unroll
        for (int j = 0; j < 4; j++)
            cp16(bd + j * (BST * 4), Bptr + (size_t)(c * KC + kb + j) * bstride);
    };

    stage(0, 0); CP_COMMIT();
    stage(1, 1); CP_COMMIT();

    int buf = 0;
    for (int c = 0; c < NCHUNK; c++) {
        if (c + 2 < NCHUNK) { stage(c + 2, (c + 2) % 3); CP_COMMIT(); CP_WAIT(2); }
        else if (c + 1 < NCHUNK) { CP_WAIT(1); }
        else { CP_WAIT(0); }
        __syncthreads();

        const float* Asb = smemf + buf * AOFF;
        const float* Bsb = smemf + BBASE + buf * BOFF;
        #pragma unroll
        for (int kk = 0; kk < 4; kk++) {
            const int k0 = kk * 8;
            unsigned af[4][4], bf[4][2];
            #pragma unroll
            for (int mt = 0; mt < 4; mt++) {
                const int rb = warp_m * 64 + mt * 16 + g;
                af[mt][0] = f2tf32(Asb[rb * AST + k0 + tig]);
                af[mt][1] = f2tf32(Asb[(rb + 8) * AST + k0 + tig]);
                af[mt][2] = f2tf32(Asb[rb * AST + k0 + tig + 4]);
                af[mt][3] = f2tf32(Asb[(rb + 8) * AST + k0 + tig + 4]);
            }
            #pragma unroll
            for (int nt = 0; nt < 4; nt++) {
                const int cb = warp_n * 32 + nt * 8 + g;
                bf[nt][0] = f2tf32(Bsb[(k0 + tig) * BST + cb]);
                bf[nt][1] = f2tf32(Bsb[(k0 + tig + 4) * BST + cb]);
            }
            #pragma unroll
            for (int mt = 0; mt < 4; mt++)
                #pragma unroll
                for (int nt = 0; nt < 4; nt++)
                    mma_tf32(acc[mt][nt], af[mt], bf[nt]);
        }
        __syncthreads();
        buf = (buf == 2) ? 0 : buf + 1;
    }

    #pragma unroll
    for (int mt = 0; mt < 4; mt++) {
        const int r0 = m0 + warp_m * 64 + mt * 16 + g;
        #pragma unroll
        for (int nt = 0; nt < 4; nt++) {
            const int col = n0 + warp_n * 32 + nt * 8 + 2 * tig;
            const float bx = bias[col], by = bias[col + 1];
            float2 v0 = { acc[mt][nt][0] + bx, acc[mt][nt][1] + by };
            float2 v1 = { acc[mt][nt][2] + bx, acc[mt][nt][3] + by };
            *(float2*)&C[(size_t)r0 * DM + col] = v0;
            *(float2*)&C[(size_t)(r0 + 8) * DM + col] = v1;
        }
    }
}

// ===========================================================================
// Flash attention, fp16 mma.sync m16n8k16, fp32 accumulate.
// Block = 128 q rows x one (b,h). 8 warps x 16 q rows. kv tiles of 64.
// Q/K smem [row][d] halfs stride 72; V smem transposed [d][kv] stride 72.
// Fragment half2 reads hit banks 4g+tig (36 words/row ≡ 4 mod 32): clean.
// P -> PV A-fragment via register packs only (no shfl, no smem).
// ===========================================================================
#define HST 72   // half stride per row
#define HSW 36   // word stride per row

__global__ __launch_bounds__(256) void flash_f16(
    const float* __restrict__ Q, const float* __restrict__ K,
    const float* __restrict__ V, float* __restrict__ Z)
{
    __shared__ __align__(16) __half ks[64 * HST];
    __shared__ __align__(16) __half vs[64 * HST];

    const int tid = threadIdx.x;
    const int wid = tid >> 5, lane = tid & 31;
    const int g = lane >> 2, tig = lane & 3;
    const int qt = gridDim.x - 1 - blockIdx.x;       // heavy tiles first
    const int bh = blockIdx.y;
    const int b = bh >> 4, h = bh & 15;
    const size_t base = ((size_t)b * SEQ * NH + h) * DH;
    const int qrow0 = qt * 128 + wid * 16;

    const int srow = tid >> 2;          // staging row 0..63
    const int sc16 = (tid & 3) * 16;    // staging d group (16 floats)
    const unsigned* ksw = (const unsigned*)ks;
    const unsigned* vsw = (const unsigned*)vs;

    // ---- Q -> register A-fragments (fp16, scale 1/8 folded; 2 passes) ----
    unsigned aq[4][4];
    #pragma unroll
    for (int pass = 0; pass < 2; pass++) {
        const int qsrow = qt * 128 + pass * 64 + srow;
        #pragma unroll
        for (int i = 0; i < 2; i++) {
            float4 q0 = *(const float4*)&Q[base + (size_t)qsrow * DM + sc16 + 8 * i];
            float4 q1 = *(const float4*)&Q[base + (size_t)qsrow * DM + sc16 + 8 * i + 4];
            uint4 u = { pack_h2(q0.x * 0.125f, q0.y * 0.125f),
                        pack_h2(q0.z * 0.125f, q0.w * 0.125f),
                        pack_h2(q1.x * 0.125f, q1.y * 0.125f),
                        pack_h2(q1.z * 0.125f, q1.w * 0.125f) };
            *(uint4*)&ks[srow * HST + sc16 + 8 * i] = u;
        }
        __syncthreads();
        if ((wid >> 2) == pass) {
            const int r = (wid & 3) * 16 + g;
            #pragma unroll
            for (int kk = 0; kk < 4; kk++) {
                aq[kk][0] = ksw[r * HSW + kk * 8 + tig];
                aq[kk][1] = ksw[(r + 8) * HSW + kk * 8 + tig];
                aq[kk][2] = ksw[r * HSW + kk * 8 + tig + 4];
                aq[kk][3] = ksw[(r + 8) * HSW + kk * 8 + tig + 4];
            }
        }
        __syncthreads();
    }

    float m0 = -1e30f, m1 = -1e30f, l0 = 0.f, l1 = 0.f;
    float oacc[8][4];
    #pragma unroll
    for (int nt = 0; nt < 8; nt++)
        #pragma unroll
        for (int i = 0; i < 4; i++) oacc[nt][i] = 0.f;

    const int vkv = tid & 63;          // V staging: transpose write
    const int vd0 = (tid >> 6) * 16;
    const int NKT = 2 * qt + 2;

    for (int kt = 0; kt < NKT; kt++) {
        const int ktb = kt * 64;
        __syncthreads();
        // K tile [kv][d] fp16
        #pragma unroll
        for (int i = 0; i < 2; i++) {
            float4 k0 = *(const float4*)&K[base + (size_t)(ktb + srow) * DM + sc16 + 8 * i];
            float4 k1 = *(const float4*)&K[base + (size_t)(ktb + srow) * DM + sc16 + 8 * i + 4];
            uint4 u = { pack_h2(k0.x, k0.y), pack_h2(k0.z, k0.w),
                        pack_h2(k1.x, k1.y), pack_h2(k1.z, k1.w) };
            *(uint4*)&ks[srow * HST + sc16 + 8 * i] = u;
        }
        // V tile transposed -> [d][kv] fp16
        #pragma unroll
        for (int i = 0; i < 4; i++) {
            float4 vv = *(const float4*)&V[base + (size_t)(ktb + vkv) * DM + vd0 + 4 * i];
            vs[(vd0 + 4 * i + 0) * HST + vkv] = __float2half_rn(vv.x);
            vs[(vd0 + 4 * i + 1) * HST + vkv] = __float2half_rn(vv.y);
            vs[(vd0 + 4 * i + 2) * HST + vkv] = __float2half_rn(vv.z);
            vs[(vd0 + 4 * i + 3) * HST + vkv] = __float2half_rn(vv.w);
        }
        __syncthreads();

        if (ktb > qrow0 + 15) continue;   // tile fully masked for this warp

        // ---- S = Q K^T (4 k-steps of 16) ----
        float sacc[8][4];
        #pragma unroll
        for (int nt = 0; nt < 8; nt++)
            #pragma unroll
            for (int i = 0; i < 4; i++) sacc[nt][i] = 0.f;

        #pragma unroll
        for (int kk = 0; kk < 4; kk++) {
            unsigned bf[8][2];
            #pragma unroll
            for (int nt = 0; nt < 8; nt++) {
                bf[nt][0] = ksw[(nt * 8 + g) * HSW + kk * 8 + tig];
                bf[nt][1] = ksw[(nt * 8 + g) * HSW + kk * 8 + tig + 4];
            }
            #pragma unroll
            for (int nt = 0; nt < 8; nt++)
                mma_f16(sacc[nt], aq[kk], bf[nt]);
        }

        // ---- causal mask (diagonal tiles only) ----
        if (ktb + 63 > qrow0) {
            #pragma unroll
            for (int nt = 0; nt < 8; nt++) {
                const int kv0 = ktb + nt * 8 + 2 * tig;
                if (kv0     > qrow0 + g)     sacc[nt][0] = -1e30f;
                if (kv0 + 1 > qrow0 + g)     sacc[nt][1] = -1e30f;
                if (kv0     > qrow0 + g + 8) sacc[nt][2] = -1e30f;
                if (kv0 + 1 > qrow0 + g + 8) sacc[nt][3] = -1e30f;
            }
        }

        // ---- online softmax ----
        float rm0 = -1e30f, rm1 = -1e30f;
        #pragma unroll
        for (int nt = 0; nt < 8; nt++) {
            rm0 = fmaxf(rm0, fmaxf(sacc[nt][0], sacc[nt][1]));
            rm1 = fmaxf(rm1, fmaxf(sacc[nt][2], sacc[nt][3]));
        }
        rm0 = fmaxf(rm0, __shfl_xor_sync(0xffffffffu, rm0, 1));
        rm0 = fmaxf(rm0, __shfl_xor_sync(0xffffffffu, rm0, 2));
        rm1 = fmaxf(rm1, __shfl_xor_sync(0xffffffffu, rm1, 1));
        rm1 = fmaxf(rm1, __shfl_xor_sync(0xffffffffu, rm1, 2));
        const float mn0 = fmaxf(m0, rm0), mn1 = fmaxf(m1, rm1);
        const float al0 = __expf(m0 - mn0), al1 = __expf(m1 - mn1);
        float rs0 = 0.f, rs1 = 0.f;
        #pragma unroll
        for (int nt = 0; nt < 8; nt++) {
            sacc[nt][0] = __expf(sacc[nt][0] - mn0); rs0 += sacc[nt][0];
            sacc[nt][1] = __expf(sacc[nt][1] - mn0); rs0 += sacc[nt][1];
            sacc[nt][2] = __expf(sacc[nt][2] - mn1); rs1 += sacc[nt][2];
            sacc[nt][3] = __expf(sacc[nt][3] - mn1); rs1 += sacc[nt][3];
        }
        rs0 += __shfl_xor_sync(0xffffffffu, rs0, 1);
        rs0 += __shfl_xor_sync(0xffffffffu, rs0, 2);
        rs1 += __shfl_xor_sync(0xffffffffu, rs1, 1);
        rs1 += __shfl_xor_sync(0xffffffffu, rs1, 2);
        l0 = l0 * al0 + rs0;  l1 = l1 * al1 + rs1;
        m0 = mn0;             m1 = mn1;
        #pragma unroll
        for (int nt = 0; nt < 8; nt++) {
            oacc[nt][0] *= al0; oacc[nt][1] *= al0;
            oacc[nt][2] *= al1; oacc[nt][3] *= al1;
        }

        // ---- O += P V : S C-fragment IS the A-fragment (pack only) ----
        #pragma unroll
        for (int kk = 0; kk < 4; kk++) {
            unsigned ap[4];
            ap[0] = pack_h2(sacc[2*kk][0],   sacc[2*kk][1]);
            ap[1] = pack_h2(sacc[2*kk][2],   sacc[2*kk][3]);
            ap[2] = pack_h2(sacc[2*kk+1][0], sacc[2*kk+1][1]);
            ap[3] = pack_h2(sacc[2*kk+1][2], sacc[2*kk+1][3]);
            unsigned bf[8][2];
            #pragma unroll
            for (int nt = 0; nt < 8; nt++) {
                bf[nt][0] = vsw[(nt * 8 + g) * HSW + kk * 8 + tig];
                bf[nt][1] = vsw[(nt * 8 + g) * HSW + kk * 8 + tig + 4];
            }
            #pragma unroll
            for (int nt = 0; nt < 8; nt++)
                mma_f16(oacc[nt], ap, bf[nt]);
        }
    }

    // ---- normalize + write z[b, s, h, d] ----
    const float i0 = 1.f / l0, i1 = 1.f / l1;
    #pragma unroll
    for (int nt = 0; nt < 8; nt++) {
        const int col = nt * 8 + 2 * tig;
        const int row = qrow0 + g;
        float2 v0 = { oacc[nt][0] * i0, oacc[nt][1] * i0 };
        float2 v1 = { oacc[nt][2] * i1, oacc[nt][3] * i1 };
        *(float2*)&Z[base + (size_t)row * DM + col] = v0;
        *(float2*)&Z[base + (size_t)(row + 8) * DM + col] = v1;
    }
}

// ---------------------------------------------------------------------------

extern "C" void kernel_launch(void* const* d_in, const int* in_sizes, int n_in,
                              void* d_out, int out_size)
{
    const float* x  = (const float*)d_in[0];
    const float* WQ = (const float*)d_in[1];
    const float* WK = (const float*)d_in[2];
    const float* WV = (const float*)d_in[3];
    const float* WO = (const float*)d_in[4];
    const float* bQ = (const float*)d_in[5];
    const float* bK = (const float*)d_in[6];
    const float* bV = (const float*)d_in[7];
    const float* bO = (const float*)d_in[8];
    float* out = (float*)d_out;

    float *q, *k, *v, *z;
    cudaGetSymbolAddress((void**)&q, g_q);
    cudaGetSymbolAddress((void**)&k, g_k);
    cudaGetSymbolAddress((void**)&v, g_v);
    cudaGetSymbolAddress((void**)&z, g_z);

    cudaFuncSetAttribute(tc_gemm<0>, cudaFuncAttributeMaxDynamicSharedMemorySize, GEMM_SMEM);
    cudaFuncSetAttribute(tc_gemm<1>, cudaFuncAttributeMaxDynamicSharedMemorySize, GEMM_SMEM);

    dim3 gg(DM / BN, MTOT / BM);        // (8, 32)
    tc_gemm<1><<<gg, 256, GEMM_SMEM>>>(x, WQ, bQ, q);
    tc_gemm<1><<<gg, 256, GEMM_SMEM>>>(x, WK, bK, k);
    tc_gemm<1><<<gg, 256, GEMM_SMEM>>>(x, WV, bV, v);
    flash_f16<<<dim3(SEQ / 128, BATCH * NH), 256>>>(q, k, v, z);
    tc_gemm<0><<<gg, 256, GEMM_SMEM>>>(z, WO, bO, out);
}

// round 9
// speedup vs baseline: 1.9887x; 1.5207x over previous
#include <cuda_runtime.h>
#include <cuda_fp16.h>
#include <cstdint>

#define SEQ   2048
#define BATCH 2
#define NH    16
#define DH    64
#define DM    1024
#define MTOT  (BATCH*SEQ)   // 4096 rows

// fp16 scratch (device globals: no allocation allowed in kernel_launch)
__device__ __half h_x [(size_t)MTOT * DM];
__device__ __half h_q [(size_t)MTOT * DM];
__device__ __half h_k [(size_t)MTOT * DM];
__device__ __half h_v [(size_t)MTOT * DM];
__device__ __half h_z [(size_t)MTOT * DM];
__device__ __half h_wq[(size_t)DM * DM];
__device__ __half h_wk[(size_t)DM * DM];
__device__ __half h_wv[(size_t)DM * DM];
__device__ __half h_wo[(size_t)DM * DM];

// ===========================================================================
// helpers
// ===========================================================================
__device__ __forceinline__ void mma_f16(float* d, const unsigned* a, const unsigned* b) {
    asm volatile("mma.sync.aligned.m16n8k16.row.col.f32.f16.f16.f32 "
        "{%0,%1,%2,%3}, {%4,%5,%6,%7}, {%8,%9}, {%0,%1,%2,%3};"
        : "+f"(d[0]), "+f"(d[1]), "+f"(d[2]), "+f"(d[3])
        : "r"(a[0]), "r"(a[1]), "r"(a[2]), "r"(a[3]), "r"(b[0]), "r"(b[1]));
}

__device__ __forceinline__ unsigned pack_h2(float lo, float hi) {
    unsigned r;
    asm("cvt.rn.f16x2.f32 %0, %1, %2;" : "=r"(r) : "f"(hi), "f"(lo));
    return r;
}

__device__ __forceinline__ unsigned smem_u32(const void* p) {
    unsigned r;
    asm("{ .reg .u64 t; cvta.to.shared.u64 t, %1; cvt.u32.u64 %0, t; }"
        : "=r"(r) : "l"(p));
    return r;
}

__device__ __forceinline__ void cp16(unsigned dst, const void* src) {
    asm volatile("cp.async.cg.shared.global [%0], [%1], 16;" :: "r"(dst), "l"(src));
}
#define CP_COMMIT()  asm volatile("cp.async.commit_group;" ::: "memory")
#define CP_WAIT(n)   asm volatile("cp.async.wait_group %0;" :: "n"(n) : "memory")

// ===========================================================================
// prep kernels
// ===========================================================================
// straight convert fp32 -> fp16 (4 elems/thread)
__global__ __launch_bounds__(256) void convx_kernel(
    const float* __restrict__ X, __half* __restrict__ Y)
{
    const size_t i = ((size_t)blockIdx.x * 256 + threadIdx.x) * 4;
    float4 v = *(const float4*)&X[i];
    uint2 u = { pack_h2(v.x, v.y), pack_h2(v.z, v.w) };
    *(uint2*)&Y[i] = u;
}

// transpose+convert+scale: X[batch][R][C] fp32 -> Y[batch*C + c][R] fp16
__global__ __launch_bounds__(256) void tconv_kernel(
    const float* __restrict__ X, __half* __restrict__ Y,
    int R, int C, float scale)
{
    __shared__ float t[32][33];
    const int r0 = blockIdx.x * 32, c0 = blockIdx.y * 32;
    const float* Xb = X + (size_t)blockIdx.z * R * C;
    __half* Yb = Y + (size_t)blockIdx.z * C * R;
    const int tx = threadIdx.x, ty = threadIdx.y;
    #pragma unroll
    for (int i = ty; i < 32; i += 8)
        t[i][tx] = Xb[(size_t)(r0 + i) * C + c0 + tx];
    __syncthreads();
    #pragma unroll
    for (int i = ty; i < 32; i += 8)
        Yb[(size_t)(c0 + i) * R + r0 + tx] = __float2half_rn(t[tx][i] * scale);
}

// ===========================================================================
// fp16 tensor GEMM, cp.async 3-stage pipeline:
//   C[4096,1024](OutT) = A[4096,1024](h) @ Wt[n][k](h) + bias*bscale
// KC=32 halfs/chunk. Smem rows stride 20 words (40 halfs): fragment reads
// bank = (g*20+tig) mod 32 -> all 32 distinct. Tiles: A/B 128x20w, 3 stages,
// total 15360 words = 61440 B dynamic.
// ===========================================================================
#define BM 128
#define BN 128
#define KCH 32             // halfs per k-chunk
#define NCHUNK (DM / KCH)  // 32
#define GSTW 20            // row stride in words
#define TOFFW 2560         // words per tile (128*20)
#define GEMM_SMEM 61440

template<int OUTF>
__global__ __launch_bounds__(256, 2) void tc_gemm_h(
    const __half* __restrict__ A, const __half* __restrict__ Wt,
    const float* __restrict__ bias, void* __restrict__ Cv, float bscale)
{
    extern __shared__ __align__(16) unsigned smemw[];
    const unsigned sbase = smem_u32(smemw);

    const int tid = threadIdx.x;
    const int wid = tid >> 5, lane = tid & 31;
    const int g = lane >> 2, tig = lane & 3;
    const int warp_m = wid & 1, warp_n = wid >> 1;
    const int m0 = blockIdx.y * BM, n0 = blockIdx.x * BN;

    const int row = tid >> 1;            // 0..127 (same row idx for A and B)
    const int hc  = (tid & 1) * 16;      // half offset within chunk
    const __half* Aptr = A  + (size_t)(m0 + row) * DM + hc;
    const __half* Bptr = Wt + (size_t)(n0 + row) * DM + hc;
    const unsigned aDst = sbase + (row * GSTW + (tid & 1) * 8) * 4;
    const unsigned bDst = aDst + 3 * TOFFW * 4;

    float acc[4][4][4];
    #pragma unroll
    for (int mt = 0; mt < 4; mt++)
        #pragma unroll
        for (int nt = 0; nt < 4; nt++)
            #pragma unroll
            for (int i = 0; i < 4; i++) acc[mt][nt][i] = 0.f;

    auto stage = [&](int c, int buf) {
        const __half* ap = Aptr + c * KCH;
        const __half* bp = Bptr + c * KCH;
        const unsigned ad = aDst + buf * (TOFFW * 4);
        const unsigned bd = bDst + buf * (TOFFW * 4);
        cp16(ad, ap); cp16(ad + 16, ap + 8);
        cp16(bd, bp); cp16(bd + 16, bp + 8);
    };

    stage(0, 0); CP_COMMIT();
    stage(1, 1); CP_COMMIT();

    int buf = 0;
    for (int c = 0; c < NCHUNK; c++) {
        if (c + 2 < NCHUNK) { stage(c + 2, (c + 2) % 3); CP_COMMIT(); CP_WAIT(2); }
        else if (c + 1 < NCHUNK) { CP_WAIT(1); }
        else { CP_WAIT(0); }
        __syncthreads();

        const unsigned* Asb = smemw + buf * TOFFW;
        const unsigned* Bsb = smemw + 3 * TOFFW + buf * TOFFW;
        #pragma unroll
        for (int kk = 0; kk < 2; kk++) {
            unsigned af[4][4], bf[4][2];
            #pragma unroll
            for (int mt = 0; mt < 4; mt++) {
                const int rb = warp_m * 64 + mt * 16 + g;
                af[mt][0] = Asb[rb * GSTW + kk * 8 + tig];
                af[mt][1] = Asb[(rb + 8) * GSTW + kk * 8 + tig];
                af[mt][2] = Asb[rb * GSTW + kk * 8 + tig + 4];
                af[mt][3] = Asb[(rb + 8) * GSTW + kk * 8 + tig + 4];
            }
            #pragma unroll
            for (int nt = 0; nt < 4; nt++) {
                const int cb = warp_n * 32 + nt * 8 + g;
                bf[nt][0] = Bsb[cb * GSTW + kk * 8 + tig];
                bf[nt][1] = Bsb[cb * GSTW + kk * 8 + tig + 4];
            }
            #pragma unroll
            for (int mt = 0; mt < 4; mt++)
                #pragma unroll
                for (int nt = 0; nt < 4; nt++)
                    mma_f16(acc[mt][nt], af[mt], bf[nt]);
        }
        __syncthreads();
        buf = (buf == 2) ? 0 : buf + 1;
    }

    #pragma unroll
    for (int mt = 0; mt < 4; mt++) {
        const int r0 = m0 + warp_m * 64 + mt * 16 + g;
        #pragma unroll
        for (int nt = 0; nt < 4; nt++) {
            const int col = n0 + warp_n * 32 + nt * 8 + 2 * tig;
            const float bx = bias[col] * bscale, by = bias[col + 1] * bscale;
            if (OUTF) {            // fp32 output
                float* C = (float*)Cv;
                float2 v0 = { acc[mt][nt][0] + bx, acc[mt][nt][1] + by };
                float2 v1 = { acc[mt][nt][2] + bx, acc[mt][nt][3] + by };
                *(float2*)&C[(size_t)r0 * DM + col] = v0;
                *(float2*)&C[(size_t)(r0 + 8) * DM + col] = v1;
            } else {               // fp16 output
                __half* C = (__half*)Cv;
                *(unsigned*)&C[(size_t)r0 * DM + col] =
                    pack_h2(acc[mt][nt][0] + bx, acc[mt][nt][1] + by);
                *(unsigned*)&C[(size_t)(r0 + 8) * DM + col] =
                    pack_h2(acc[mt][nt][2] + bx, acc[mt][nt][3] + by);
            }
        }
    }
}

// ===========================================================================
// Flash attention, fp16 in/out, m16n8k16. Q pre-scaled by 1/8 (folded into
// WQt/bQ). Block = 128 q rows x one (b,h). 8 warps x 16 q rows. kv tiles 64.
// Q/K smem [row][d] halfs stride 72; V transposed [d][kv] stride 72.
// ===========================================================================
#define HST 72   // half stride per row
#define HSW 36   // word stride per row

__global__ __launch_bounds__(256) void flash_h(
    const __half* __restrict__ Q, const __half* __restrict__ K,
    const __half* __restrict__ V, __half* __restrict__ Z)
{
    __shared__ __align__(16) __half ks[64 * HST];
    __shared__ __align__(16) __half vs[64 * HST];
    const unsigned ksb = smem_u32(ks);

    const int tid = threadIdx.x;
    const int wid = tid >> 5, lane = tid & 31;
    const int g = lane >> 2, tig = lane & 3;
    const int qt = gridDim.x - 1 - blockIdx.x;       // heavy tiles first
    const int bh = blockIdx.y;
    const int b = bh >> 4, h = bh & 15;
    const size_t base = ((size_t)b * SEQ * NH + h) * DH;
    const int qrow0 = qt * 128 + wid * 16;

    const int srow = tid >> 2;          // staging row 0..63
    const int sc16 = (tid & 3) * 16;    // half offset within 64-half row
    const unsigned sdst = ksb + srow * 144 + (tid & 3) * 32;
    const unsigned* ksw = (const unsigned*)ks;
    const unsigned* vsw = (const unsigned*)vs;

    // ---- Q -> register A-fragments (pre-scaled fp16; 2 cp.async passes) ----
    unsigned aq[4][4];
    #pragma unroll
    for (int pass = 0; pass < 2; pass++) {
        const __half* qp = Q + base + (size_t)(qt * 128 + pass * 64 + srow) * DM + sc16;
        cp16(sdst, qp); cp16(sdst + 16, qp + 8);
        CP_COMMIT(); CP_WAIT(0);
        __syncthreads();
        if ((wid >> 2) == pass) {
            const int r = (wid & 3) * 16 + g;
            #pragma unroll
            for (int kk = 0; kk < 4; kk++) {
                aq[kk][0] = ksw[r * HSW + kk * 8 + tig];
                aq[kk][1] = ksw[(r + 8) * HSW + kk * 8 + tig];
                aq[kk][2] = ksw[r * HSW + kk * 8 + tig + 4];
                aq[kk][3] = ksw[(r + 8) * HSW + kk * 8 + tig + 4];
            }
        }
        __syncthreads();
    }

    float m0 = -1e30f, m1 = -1e30f, l0 = 0.f, l1 = 0.f;
    float oacc[8][4];
    #pragma unroll
    for (int nt = 0; nt < 8; nt++)
        #pragma unroll
        for (int i = 0; i < 4; i++) oacc[nt][i] = 0.f;

    const int vkv = tid & 63;          // V staging: transpose write
    const int vd0 = (tid >> 6) * 16;
    const int NKT = 2 * qt + 2;

    for (int kt = 0; kt < NKT; kt++) {
        const int ktb = kt * 64;
        __syncthreads();
        // K tile via cp.async
        {
            const __half* kp = K + base + (size_t)(ktb + srow) * DM + sc16;
            cp16(sdst, kp); cp16(sdst + 16, kp + 8);
            CP_COMMIT();
        }
        // V tile transposed -> [d][kv]
        #pragma unroll
        for (int i = 0; i < 2; i++) {
            uint4 vv = *(const uint4*)&V[base + (size_t)(ktb + vkv) * DM + vd0 + 8 * i];
            const __half* hp = (const __half*)&vv;
            #pragma unroll
            for (int j = 0; j < 8; j++)
                vs[(vd0 + 8 * i + j) * HST + vkv] = hp[j];
        }
        CP_WAIT(0);
        __syncthreads();

        if (ktb > qrow0 + 15) continue;   // tile fully masked for this warp

        // ---- S = Q K^T (4 k-steps of 16) ----
        float sacc[8][4];
        #pragma unroll
        for (int nt = 0; nt < 8; nt++)
            #pragma unroll
            for (int i = 0; i < 4; i++) sacc[nt][i] = 0.f;

        #pragma unroll
        for (int kk = 0; kk < 4; kk++) {
            unsigned bf[8][2];
            #pragma unroll
            for (int nt = 0; nt < 8; nt++) {
                bf[nt][0] = ksw[(nt * 8 + g) * HSW + kk * 8 + tig];
                bf[nt][1] = ksw[(nt * 8 + g) * HSW + kk * 8 + tig + 4];
            }
            #pragma unroll
            for (int nt = 0; nt < 8; nt++)
                mma_f16(sacc[nt], aq[kk], bf[nt]);
        }

        // ---- causal mask (diagonal tiles only) ----
        if (ktb + 63 > qrow0) {
            #pragma unroll
            for (int nt = 0; nt < 8; nt++) {
                const int kv0 = ktb + nt * 8 + 2 * tig;
                if (kv0     > qrow0 + g)     sacc[nt][0] = -1e30f;
                if (kv0 + 1 > qrow0 + g)     sacc[nt][1] = -1e30f;
                if (kv0     > qrow0 + g + 8) sacc[nt][2] = -1e30f;
                if (kv0 + 1 > qrow0 + g + 8) sacc[nt][3] = -1e30f;
            }
        }

        // ---- online softmax ----
        float rm0 = -1e30f, rm1 = -1e30f;
        #pragma unroll
        for (int nt = 0; nt < 8; nt++) {
            rm0 = fmaxf(rm0, fmaxf(sacc[nt][0], sacc[nt][1]));
            rm1 = fmaxf(rm1, fmaxf(sacc[nt][2], sacc[nt][3]));
        }
        rm0 = fmaxf(rm0, __shfl_xor_sync(0xffffffffu, rm0, 1));
        rm0 = fmaxf(rm0, __shfl_xor_sync(0xffffffffu, rm0, 2));
        rm1 = fmaxf(rm1, __shfl_xor_sync(0xffffffffu, rm1, 1));
        rm1 = fmaxf(rm1, __shfl_xor_sync(0xffffffffu, rm1, 2));
        const float mn0 = fmaxf(m0, rm0), mn1 = fmaxf(m1, rm1);
        const float al0 = __expf(m0 - mn0), al1 = __expf(m1 - mn1);
        float rs0 = 0.f, rs1 = 0.f;
        #pragma unroll
        for (int nt = 0; nt < 8; nt++) {
            sacc[nt][0] = __expf(sacc[nt][0] - mn0); rs0 += sacc[nt][0];
            sacc[nt][1] = __expf(sacc[nt][1] - mn0); rs0 += sacc[nt][1];
            sacc[nt][2] = __expf(sacc[nt][2] - mn1); rs1 += sacc[nt][2];
            sacc[nt][3] = __expf(sacc[nt][3] - mn1); rs1 += sacc[nt][3];
        }
        rs0 += __shfl_xor_sync(0xffffffffu, rs0, 1);
        rs0 += __shfl_xor_sync(0xffffffffu, rs0, 2);
        rs1 += __shfl_xor_sync(0xffffffffu, rs1, 1);
        rs1 += __shfl_xor_sync(0xffffffffu, rs1, 2);
        l0 = l0 * al0 + rs0;  l1 = l1 * al1 + rs1;
        m0 = mn0;             m1 = mn1;
        #pragma unroll
        for (int nt = 0; nt < 8; nt++) {
            oacc[nt][0] *= al0; oacc[nt][1] *= al0;
            oacc[nt][2] *= al1; oacc[nt][3] *= al1;
        }

        // ---- O += P V : S C-fragment IS the A-fragment (pack only) ----
        #pragma unroll
        for (int kk = 0; kk < 4; kk++) {
            unsigned ap[4];
            ap[0] = pack_h2(sacc[2*kk][0],   sacc[2*kk][1]);
            ap[1] = pack_h2(sacc[2*kk][2],   sacc[2*kk][3]);
            ap[2] = pack_h2(sacc[2*kk+1][0], sacc[2*kk+1][1]);
            ap[3] = pack_h2(sacc[2*kk+1][2], sacc[2*kk+1][3]);
            unsigned bf[8][2];
            #pragma unroll
            for (int nt = 0; nt < 8; nt++) {
                bf[nt][0] = vsw[(nt * 8 + g) * HSW + kk * 8 + tig];
                bf[nt][1] = vsw[(nt * 8 + g) * HSW + kk * 8 + tig + 4];
            }
            #pragma unroll
            for (int nt = 0; nt < 8; nt++)
                mma_f16(oacc[nt], ap, bf[nt]);
        }
    }

    // ---- normalize + write z (fp16) ----
    const float i0 = 1.f / l0, i1 = 1.f / l1;
    #pragma unroll
    for (int nt = 0; nt < 8; nt++) {
        const int col = nt * 8 + 2 * tig;
        const int row = qrow0 + g;
        *(unsigned*)&Z[base + (size_t)row * DM + col] =
            pack_h2(oacc[nt][0] * i0, oacc[nt][1] * i0);
        *(unsigned*)&Z[base + (size_t)(row + 8) * DM + col] =
            pack_h2(oacc[nt][2] * i1, oacc[nt][3] * i1);
    }
}

// ---------------------------------------------------------------------------

extern "C" void kernel_launch(void* const* d_in, const int* in_sizes, int n_in,
                              void* d_out, int out_size)
{
    const float* x  = (const float*)d_in[0];
    const float* WQ = (const float*)d_in[1];
    const float* WK = (const float*)d_in[2];
    const float* WV = (const float*)d_in[3];
    const float* WO = (const float*)d_in[4];
    const float* bQ = (const float*)d_in[5];
    const float* bK = (const float*)d_in[6];
    const float* bV = (const float*)d_in[7];
    const float* bO = (const float*)d_in[8];
    float* out = (float*)d_out;

    __half *xh, *qh, *kh, *vh, *zh, *wqt, *wkt, *wvt, *wot;
    cudaGetSymbolAddress((void**)&xh,  h_x);
    cudaGetSymbolAddress((void**)&qh,  h_q);
    cudaGetSymbolAddress((void**)&kh,  h_k);
    cudaGetSymbolAddress((void**)&vh,  h_v);
    cudaGetSymbolAddress((void**)&zh,  h_z);
    cudaGetSymbolAddress((void**)&wqt, h_wq);
    cudaGetSymbolAddress((void**)&wkt, h_wk);
    cudaGetSymbolAddress((void**)&wvt, h_wv);
    cudaGetSymbolAddress((void**)&wot, h_wo);

    cudaFuncSetAttribute(tc_gemm_h<0>, cudaFuncAttributeMaxDynamicSharedMemorySize, GEMM_SMEM);
    cudaFuncSetAttribute(tc_gemm_h<1>, cudaFuncAttributeMaxDynamicSharedMemorySize, GEMM_SMEM);

    // prep: convert x; transpose+convert weights (scale 1/8 folded into WQt)
    convx_kernel<<<(MTOT * DM) / 1024, 256>>>(x, xh);
    tconv_kernel<<<dim3(32, 2, 16), dim3(32, 8)>>>(WQ, wqt, DM, DH, 0.125f);
    tconv_kernel<<<dim3(32, 2, 16), dim3(32, 8)>>>(WK, wkt, DM, DH, 1.f);
    tconv_kernel<<<dim3(32, 2, 16), dim3(32, 8)>>>(WV, wvt, DM, DH, 1.f);
    tconv_kernel<<<dim3(32, 32, 1), dim3(32, 8)>>>(WO, wot, DM, DM, 1.f);

    dim3 gg(DM / BN, MTOT / BM);        // (8, 32)
    tc_gemm_h<0><<<gg, 256, GEMM_SMEM>>>(xh, wqt, bQ, qh, 0.125f);
    tc_gemm_h<0><<<gg, 256, GEMM_SMEM>>>(xh, wkt, bK, kh, 1.f);
    tc_gemm_h<0><<<gg, 256, GEMM_SMEM>>>(xh, wvt, bV, vh, 1.f);
    flash_h<<<dim3(SEQ / 128, BATCH * NH), 256>>>(qh, kh, vh, zh);
    tc_gemm_h<1><<<gg, 256, GEMM_SMEM>>>(zh, wot, bO, out, 1.f);
}

// round 11
// speedup vs baseline: 2.0589x; 1.0353x over previous
#include <cuda_runtime.h>
#include <cuda_fp16.h>
#include <cstdint>

#define SEQ   2048
#define BATCH 2
#define NH    16
#define DH    64
#define DM    1024
#define MTOT  (BATCH*SEQ)   // 4096 rows

// fp16 scratch (device globals: no allocation allowed in kernel_launch)
__device__ __half h_x [(size_t)MTOT * DM];
__device__ __half h_q [(size_t)MTOT * DM];
__device__ __half h_k [(size_t)MTOT * DM];
__device__ __half h_v [(size_t)MTOT * DM];
__device__ __half h_z [(size_t)MTOT * DM];
__device__ __half h_wq[(size_t)DM * DM];
__device__ __half h_wk[(size_t)DM * DM];
__device__ __half h_wv[(size_t)DM * DM];
__device__ __half h_wo[(size_t)DM * DM];

// ===========================================================================
// helpers
// ===========================================================================
__device__ __forceinline__ void mma_f16(float* d, const unsigned* a, const unsigned* b) {
    asm volatile("mma.sync.aligned.m16n8k16.row.col.f32.f16.f16.f32 "
        "{%0,%1,%2,%3}, {%4,%5,%6,%7}, {%8,%9}, {%0,%1,%2,%3};"
        : "+f"(d[0]), "+f"(d[1]), "+f"(d[2]), "+f"(d[3])
        : "r"(a[0]), "r"(a[1]), "r"(a[2]), "r"(a[3]), "r"(b[0]), "r"(b[1]));
}

__device__ __forceinline__ unsigned pack_h2(float lo, float hi) {
    unsigned r;
    asm("cvt.rn.f16x2.f32 %0, %1, %2;" : "=r"(r) : "f"(hi), "f"(lo));
    return r;
}

__device__ __forceinline__ unsigned smem_u32(const void* p) {
    unsigned r;
    asm("{ .reg .u64 t; cvta.to.shared.u64 t, %1; cvt.u32.u64 %0, t; }"
        : "=r"(r) : "l"(p));
    return r;
}

__device__ __forceinline__ void cp16(unsigned dst, const void* src) {
    asm volatile("cp.async.cg.shared.global [%0], [%1], 16;" :: "r"(dst), "l"(src));
}
#define CP_COMMIT()  asm volatile("cp.async.commit_group;" ::: "memory")
#define CP_WAIT(n)   asm volatile("cp.async.wait_group %0;" :: "n"(n) : "memory")

// ===========================================================================
// prep kernels
// ===========================================================================
__global__ __launch_bounds__(256) void convx_kernel(
    const float* __restrict__ X, __half* __restrict__ Y)
{
    const size_t i = ((size_t)blockIdx.x * 256 + threadIdx.x) * 4;
    float4 v = *(const float4*)&X[i];
    uint2 u = { pack_h2(v.x, v.y), pack_h2(v.z, v.w) };
    *(uint2*)&Y[i] = u;
}

// transpose+convert+scale: X[batch][R][C] fp32 -> Y[batch*C + c][R] fp16
__global__ __launch_bounds__(256) void tconv_kernel(
    const float* __restrict__ X, __half* __restrict__ Y,
    int R, int C, float scale)
{
    __shared__ float t[32][33];
    const int r0 = blockIdx.x * 32, c0 = blockIdx.y * 32;
    const float* Xb = X + (size_t)blockIdx.z * R * C;
    __half* Yb = Y + (size_t)blockIdx.z * C * R;
    const int tx = threadIdx.x, ty = threadIdx.y;
    #pragma unroll
    for (int i = ty; i < 32; i += 8)
        t[i][tx] = Xb[(size_t)(r0 + i) * C + c0 + tx];
    __syncthreads();
    #pragma unroll
    for (int i = ty; i < 32; i += 8)
        Yb[(size_t)(c0 + i) * R + r0 + tx] = __float2half_rn(t[tx][i] * scale);
}

// ===========================================================================
// fp16 tensor GEMM core (cp.async 3-stage). C = A @ Wt[n][k] + bias*bscale
// ===========================================================================
#define BM 128
#define BN 128
#define KCH 32             // halfs per k-chunk
#define NCHUNK (DM / KCH)  // 32
#define GSTW 20            // row stride in words
#define TOFFW 2560         // words per tile (128*20)
#define GEMM_SMEM 61440

template<int OUTF>
__device__ __forceinline__ void gemm_body(
    const __half* __restrict__ A, const __half* __restrict__ Wt,
    const float* __restrict__ bias, void* __restrict__ Cv, float bscale,
    unsigned* smemw, int m0, int n0)
{
    const unsigned sbase = smem_u32(smemw);
    const int tid = threadIdx.x;
    const int wid = tid >> 5, lane = tid & 31;
    const int g = lane >> 2, tig = lane & 3;
    const int warp_m = wid & 1, warp_n = wid >> 1;

    const int row = tid >> 1;
    const int hc  = (tid & 1) * 16;
    const __half* Aptr = A  + (size_t)(m0 + row) * DM + hc;
    const __half* Bptr = Wt + (size_t)(n0 + row) * DM + hc;
    const unsigned aDst = sbase + (row * GSTW + (tid & 1) * 8) * 4;
    const unsigned bDst = aDst + 3 * TOFFW * 4;

    float acc[4][4][4];
    #pragma unroll
    for (int mt = 0; mt < 4; mt++)
        #pragma unroll
        for (int nt = 0; nt < 4; nt++)
            #pragma unroll
            for (int i = 0; i < 4; i++) acc[mt][nt][i] = 0.f;

    auto stage = [&](int c, int buf) {
        const __half* ap = Aptr + c * KCH;
        const __half* bp = Bptr + c * KCH;
        const unsigned ad = aDst + buf * (TOFFW * 4);
        const unsigned bd = bDst + buf * (TOFFW * 4);
        cp16(ad, ap); cp16(ad + 16, ap + 8);
        cp16(bd, bp); cp16(bd + 16, bp + 8);
    };

    stage(0, 0); CP_COMMIT();
    stage(1, 1); CP_COMMIT();

    int buf = 0;
    for (int c = 0; c < NCHUNK; c++) {
        if (c + 2 < NCHUNK) { stage(c + 2, (c + 2) % 3); CP_COMMIT(); CP_WAIT(2); }
        else if (c + 1 < NCHUNK) { CP_WAIT(1); }
        else { CP_WAIT(0); }
        __syncthreads();

        const unsigned* Asb = smemw + buf * TOFFW;
        const unsigned* Bsb = smemw + 3 * TOFFW + buf * TOFFW;
        #pragma unroll
        for (int kk = 0; kk < 2; kk++) {
            unsigned af[4][4], bf[4][2];
            #pragma unroll
            for (int mt = 0; mt < 4; mt++) {
                const int rb = warp_m * 64 + mt * 16 + g;
                af[mt][0] = Asb[rb * GSTW + kk * 8 + tig];
                af[mt][1] = Asb[(rb + 8) * GSTW + kk * 8 + tig];
                af[mt][2] = Asb[rb * GSTW + kk * 8 + tig + 4];
                af[mt][3] = Asb[(rb + 8) * GSTW + kk * 8 + tig + 4];
            }
            #pragma unroll
            for (int nt = 0; nt < 4; nt++) {
                const int cb = warp_n * 32 + nt * 8 + g;
                bf[nt][0] = Bsb[cb * GSTW + kk * 8 + tig];
                bf[nt][1] = Bsb[cb * GSTW + kk * 8 + tig + 4];
            }
            #pragma unroll
            for (int mt = 0; mt < 4; mt++)
                #pragma unroll
                for (int nt = 0; nt < 4; nt++)
                    mma_f16(acc[mt][nt], af[mt], bf[nt]);
        }
        __syncthreads();
        buf = (buf == 2) ? 0 : buf + 1;
    }

    #pragma unroll
    for (int mt = 0; mt < 4; mt++) {
        const int r0 = m0 + warp_m * 64 + mt * 16 + g;
        #pragma unroll
        for (int nt = 0; nt < 4; nt++) {
            const int col = n0 + warp_n * 32 + nt * 8 + 2 * tig;
            const float bx = bias[col] * bscale, by = bias[col + 1] * bscale;
            if (OUTF) {
                float* C = (float*)Cv;
                float2 v0 = { acc[mt][nt][0] + bx, acc[mt][nt][1] + by };
                float2 v1 = { acc[mt][nt][2] + bx, acc[mt][nt][3] + by };
                *(float2*)&C[(size_t)r0 * DM + col] = v0;
                *(float2*)&C[(size_t)(r0 + 8) * DM + col] = v1;
            } else {
                __half* C = (__half*)Cv;
                *(unsigned*)&C[(size_t)r0 * DM + col] =
                    pack_h2(acc[mt][nt][0] + bx, acc[mt][nt][1] + by);
                *(unsigned*)&C[(size_t)(r0 + 8) * DM + col] =
                    pack_h2(acc[mt][nt][2] + bx, acc[mt][nt][3] + by);
            }
        }
    }
}

// fused QKV: blockIdx.z selects {Q, K, V}
__global__ __launch_bounds__(256, 2) void tc_gemm_qkv(
    const __half* __restrict__ A,
    const __half* __restrict__ W0, const __half* __restrict__ W1,
    const __half* __restrict__ W2,
    const float* __restrict__ b0, const float* __restrict__ b1,
    const float* __restrict__ b2,
    __half* __restrict__ C0, __half* __restrict__ C1, __half* __restrict__ C2)
{
    extern __shared__ __align__(16) unsigned smemw[];
    const int z = blockIdx.z;
    const __half* Wt = (z == 0) ? W0 : (z == 1) ? W1 : W2;
    const float* bias = (z == 0) ? b0 : (z == 1) ? b1 : b2;
    __half* C = (z == 0) ? C0 : (z == 1) ? C1 : C2;
    const float bscale = (z == 0) ? 0.125f : 1.f;
    gemm_body<0>(A, Wt, bias, C, bscale, smemw, blockIdx.y * BM, blockIdx.x * BN);
}

__global__ __launch_bounds__(256, 2) void tc_gemm_out(
    const __half* __restrict__ A, const __half* __restrict__ Wt,
    const float* __restrict__ bias, float* __restrict__ C)
{
    extern __shared__ __align__(16) unsigned smemw[];
    gemm_body<1>(A, Wt, bias, C, 1.f, smemw, blockIdx.y * BM, blockIdx.x * BN);
}

// ===========================================================================
// Flash attention, fp16, m16n8k16, double-buffered K/V pipeline.
// Block = 128 q rows x one (b,h). 8 warps x 16 q rows. kv tiles of 64.
// K via cp.async; V via LDG -> (deferred, post-compute) transpose STS.
// One __syncthreads per tile. Q pre-scaled by 1/8 (folded into WQt/bQ).
// ===========================================================================
#define HST 72   // half stride per row
#define HSW 36   // word stride per row
#define KVBUF (64 * HST)   // halfs per buffer

__global__ __launch_bounds__(256) void flash_h(
    const __half* __restrict__ Q, const __half* __restrict__ K,
    const __half* __restrict__ V, __half* __restrict__ Z)
{
    __shared__ __align__(16) __half ks[2 * KVBUF];
    __shared__ __align__(16) __half vs[2 * KVBUF];
    const unsigned ksb = smem_u32(ks);

    const int tid = threadIdx.x;
    const int wid = tid >> 5, lane = tid & 31;
    const int g = lane >> 2, tig = lane & 3;
    const int qt = gridDim.x - 1 - blockIdx.x;       // heavy tiles first
    const int bh = blockIdx.y;
    const int b = bh >> 4, h = bh & 15;
    const size_t base = ((size_t)b * SEQ * NH + h) * DH;
    const int qrow0 = qt * 128 + wid * 16;

    const int srow = tid >> 2;          // staging row 0..63
    const int sc16 = (tid & 3) * 16;    // half offset within 64-half row
    const unsigned sdst = ksb + srow * 144 + (tid & 3) * 32;

    // ---- Q -> register A-fragments (pre-scaled fp16; 2 cp.async passes) ----
    unsigned aq[4][4];
    #pragma unroll
    for (int pass = 0; pass < 2; pass++) {
        const __half* qp = Q + base + (size_t)(qt * 128 + pass * 64 + srow) * DM + sc16;
        cp16(sdst, qp); cp16(sdst + 16, qp + 8);
        CP_COMMIT(); CP_WAIT(0);
        __syncthreads();
        if ((wid >> 2) == pass) {
            const unsigned* ksw = (const unsigned*)ks;
            const int r = (wid & 3) * 16 + g;
            #pragma unroll
            for (int kk = 0; kk < 4; kk++) {
                aq[kk][0] = ksw[r * HSW + kk * 8 + tig];
                aq[kk][1] = ksw[(r + 8) * HSW + kk * 8 + tig];
                aq[kk][2] = ksw[r * HSW + kk * 8 + tig + 4];
                aq[kk][3] = ksw[(r + 8) * HSW + kk * 8 + tig + 4];
            }
        }
        __syncthreads();
    }

    float m0 = -1e30f, m1 = -1e30f, l0 = 0.f, l1 = 0.f;
    float oacc[8][4];
    #pragma unroll
    for (int nt = 0; nt < 8; nt++)
        #pragma unroll
        for (int i = 0; i < 4; i++) oacc[nt][i] = 0.f;

    const int vkv = tid & 63;          // V staging row
    const int vd0 = (tid >> 6) * 16;   // V staging d group
    const int NKT = 2 * qt + 2;

    // prologue: tile 0 into buf 0
    {
        const __half* kp = K + base + (size_t)srow * DM + sc16;
        cp16(sdst, kp); cp16(sdst + 16, kp + 8);
        CP_COMMIT();
        uint4 v0 = *(const uint4*)&V[base + (size_t)vkv * DM + vd0];
        uint4 v1 = *(const uint4*)&V[base + (size_t)vkv * DM + vd0 + 8];
        const __half* hp0 = (const __half*)&v0;
        const __half* hp1 = (const __half*)&v1;
        #pragma unroll
        for (int j = 0; j < 8; j++) {
            vs[(vd0 + j) * HST + vkv] = hp0[j];
            vs[(vd0 + 8 + j) * HST + vkv] = hp1[j];
        }
        CP_WAIT(0);
        __syncthreads();
    }

    for (int kt = 0; kt < NKT; kt++) {
        const int ktb = kt * 64;
        const int buf = kt & 1, nbuf = buf ^ 1;
        uint4 pv0, pv1;
        const bool pre = (kt + 1 < NKT);
        if (pre) {
            // issue next K cp.async + next V LDG (latency hidden by compute)
            const __half* kp = K + base + (size_t)(ktb + 64 + srow) * DM + sc16;
            const unsigned kd = sdst + nbuf * (KVBUF * 2);
            cp16(kd, kp); cp16(kd + 16, kp + 8);
            CP_COMMIT();
            pv0 = *(const uint4*)&V[base + (size_t)(ktb + 64 + vkv) * DM + vd0];
            pv1 = *(const uint4*)&V[base + (size_t)(ktb + 64 + vkv) * DM + vd0 + 8];
        }

        if (ktb <= qrow0 + 15) {
            const unsigned* ksw = (const unsigned*)(ks + buf * KVBUF);
            const unsigned* vsw = (const unsigned*)(vs + buf * KVBUF);

            // ---- S = Q K^T ----
            float sacc[8][4];
            #pragma unroll
            for (int nt = 0; nt < 8; nt++)
                #pragma unroll
                for (int i = 0; i < 4; i++) sacc[nt][i] = 0.f;

            #pragma unroll
            for (int kk = 0; kk < 4; kk++) {
                unsigned bf[8][2];
                #pragma unroll
                for (int nt = 0; nt < 8; nt++) {
                    bf[nt][0] = ksw[(nt * 8 + g) * HSW + kk * 8 + tig];
                    bf[nt][1] = ksw[(nt * 8 + g) * HSW + kk * 8 + tig + 4];
                }
                #pragma unroll
                for (int nt = 0; nt < 8; nt++)
                    mma_f16(sacc[nt], aq[kk], bf[nt]);
            }

            // ---- causal mask (diagonal tiles only) ----
            if (ktb + 63 > qrow0) {
                #pragma unroll
                for (int nt = 0; nt < 8; nt++) {
                    const int kv0 = ktb + nt * 8 + 2 * tig;
                    if (kv0     > qrow0 + g)     sacc[nt][0] = -1e30f;
                    if (kv0 + 1 > qrow0 + g)     sacc[nt][1] = -1e30f;
                    if (kv0     > qrow0 + g + 8) sacc[nt][2] = -1e30f;
                    if (kv0 + 1 > qrow0 + g + 8) sacc[nt][3] = -1e30f;
                }
            }

            // ---- online softmax ----
            float rm0 = -1e30f, rm1 = -1e30f;
            #pragma unroll
            for (int nt = 0; nt < 8; nt++) {
                rm0 = fmaxf(rm0, fmaxf(sacc[nt][0], sacc[nt][1]));
                rm1 = fmaxf(rm1, fmaxf(sacc[nt][2], sacc[nt][3]));
            }
            rm0 = fmaxf(rm0, __shfl_xor_sync(0xffffffffu, rm0, 1));
            rm0 = fmaxf(rm0, __shfl_xor_sync(0xffffffffu, rm0, 2));
            rm1 = fmaxf(rm1, __shfl_xor_sync(0xffffffffu, rm1, 1));
            rm1 = fmaxf(rm1, __shfl_xor_sync(0xffffffffu, rm1, 2));
            const float mn0 = fmaxf(m0, rm0), mn1 = fmaxf(m1, rm1);
            const float al0 = __expf(m0 - mn0), al1 = __expf(m1 - mn1);
            float rs0 = 0.f, rs1 = 0.f;
            #pragma unroll
            for (int nt = 0; nt < 8; nt++) {
                sacc[nt][0] = __expf(sacc[nt][0] - mn0); rs0 += sacc[nt][0];
                sacc[nt][1] = __expf(sacc[nt][1] - mn0); rs0 += sacc[nt][1];
                sacc[nt][2] = __expf(sacc[nt][2] - mn1); rs1 += sacc[nt][2];
                sacc[nt][3] = __expf(sacc[nt][3] - mn1); rs1 += sacc[nt][3];
            }
            rs0 += __shfl_xor_sync(0xffffffffu, rs0, 1);
            rs0 += __shfl_xor_sync(0xffffffffu, rs0, 2);
            rs1 += __shfl_xor_sync(0xffffffffu, rs1, 1);
            rs1 += __shfl_xor_sync(0xffffffffu, rs1, 2);
            l0 = l0 * al0 + rs0;  l1 = l1 * al1 + rs1;
            m0 = mn0;             m1 = mn1;
            #pragma unroll
            for (int nt = 0; nt < 8; nt++) {
                oacc[nt][0] *= al0; oacc[nt][1] *= al0;
                oacc[nt][2] *= al1; oacc[nt][3] *= al1;
            }

            // ---- O += P V : S C-fragment IS the A-fragment ----
            #pragma unroll
            for (int kk = 0; kk < 4; kk++) {
                unsigned ap[4];
                ap[0] = pack_h2(sacc[2*kk][0],   sacc[2*kk][1]);
                ap[1] = pack_h2(sacc[2*kk][2],   sacc[2*kk][3]);
                ap[2] = pack_h2(sacc[2*kk+1][0], sacc[2*kk+1][1]);
                ap[3] = pack_h2(sacc[2*kk+1][2], sacc[2*kk+1][3]);
                unsigned bf[8][2];
                #pragma unroll
                for (int nt = 0; nt < 8; nt++) {
                    bf[nt][0] = vsw[(nt * 8 + g) * HSW + kk * 8 + tig];
                    bf[nt][1] = vsw[(nt * 8 + g) * HSW + kk * 8 + tig + 4];
                }
                #pragma unroll
                for (int nt = 0; nt < 8; nt++)
                    mma_f16(oacc[nt], ap, bf[nt]);
            }
        }

        if (pre) {
            // deferred V transpose STS into next buffer (safe: all warps done
            // reading it since the barrier at the end of the previous iter)
            __half* vb = vs + nbuf * KVBUF;
            const __half* hp0 = (const __half*)&pv0;
            const __half* hp1 = (const __half*)&pv1;
            #pragma unroll
            for (int j = 0; j < 8; j++) {
                vb[(vd0 + j) * HST + vkv] = hp0[j];
                vb[(vd0 + 8 + j) * HST + vkv] = hp1[j];
            }
            CP_WAIT(0);
        }
        __syncthreads();
    }

    // ---- normalize + write z (fp16) ----
    const float i0 = 1.f / l0, i1 = 1.f / l1;
    #pragma unroll
    for (int nt = 0; nt < 8; nt++) {
        const int col = nt * 8 + 2 * tig;
        const int row = qrow0 + g;
        *(unsigned*)&Z[base + (size_t)row * DM + col] =
            pack_h2(oacc[nt][0] * i0, oacc[nt][1] * i0);
        *(unsigned*)&Z[base + (size_t)(row + 8) * DM + col] =
            pack_h2(oacc[nt][2] * i1, oacc[nt][3] * i1);
    }
}

// ---------------------------------------------------------------------------

extern "C" void kernel_launch(void* const* d_in, const int* in_sizes, int n_in,
                              void* d_out, int out_size)
{
    const float* x  = (const float*)d_in[0];
    const float* WQ = (const float*)d_in[1];
    const float* WK = (const float*)d_in[2];
    const float* WV = (const float*)d_in[3];
    const float* WO = (const float*)d_in[4];
    const float* bQ = (const float*)d_in[5];
    const float* bK = (const float*)d_in[6];
    const float* bV = (const float*)d_in[7];
    const float* bO = (const float*)d_in[8];
    float* out = (float*)d_out;

    __half *xh, *qh, *kh, *vh, *zh, *wqt, *wkt, *wvt, *wot;
    cudaGetSymbolAddress((void**)&xh,  h_x);
    cudaGetSymbolAddress((void**)&qh,  h_q);
    cudaGetSymbolAddress((void**)&kh,  h_k);
    cudaGetSymbolAddress((void**)&vh,  h_v);
    cudaGetSymbolAddress((void**)&zh,  h_z);
    cudaGetSymbolAddress((void**)&wqt, h_wq);
    cudaGetSymbolAddress((void**)&wkt, h_wk);
    cudaGetSymbolAddress((void**)&wvt, h_wv);
    cudaGetSymbolAddress((void**)&wot, h_wo);

    cudaFuncSetAttribute(tc_gemm_qkv, cudaFuncAttributeMaxDynamicSharedMemorySize, GEMM_SMEM);
    cudaFuncSetAttribute(tc_gemm_out, cudaFuncAttributeMaxDynamicSharedMemorySize, GEMM_SMEM);

    // prep: convert x; transpose+convert weights (scale 1/8 folded into WQt)
    convx_kernel<<<(MTOT * DM) / 1024, 256>>>(x, xh);
    tconv_kernel<<<dim3(32, 2, 16), dim3(32, 8)>>>(WQ, wqt, DM, DH, 0.125f);
    tconv_kernel<<<dim3(32, 2, 16), dim3(32, 8)>>>(WK, wkt, DM, DH, 1.f);
    tconv_kernel<<<dim3(32, 2, 16), dim3(32, 8)>>>(WV, wvt, DM, DH, 1.f);
    tconv_kernel<<<dim3(32, 32, 1), dim3(32, 8)>>>(WO, wot, DM, DM, 1.f);

    tc_gemm_qkv<<<dim3(DM / BN, MTOT / BM, 3), 256, GEMM_SMEM>>>(
        xh, wqt, wkt, wvt, bQ, bK, bV, qh, kh, vh);
    flash_h<<<dim3(SEQ / 128, BATCH * NH), 256>>>(qh, kh, vh, zh);
    tc_gemm_out<<<dim3(DM / BN, MTOT / BM), 256, GEMM_SMEM>>>(zh, wot, bO, out);
}

// round 12
// speedup vs baseline: 2.0750x; 1.0078x over previous
#include <cuda_runtime.h>
#include <cuda_fp16.h>
#include <cstdint>

#define SEQ   2048
#define BATCH 2
#define NH    16
#define DH    64
#define DM    1024
#define MTOT  (BATCH*SEQ)   // 4096 rows

// fp16 scratch (device globals: no allocation allowed in kernel_launch)
__device__ __half h_x [(size_t)MTOT * DM];
__device__ __half h_q [(size_t)MTOT * DM];
__device__ __half h_k [(size_t)MTOT * DM];
__device__ __half h_v [(size_t)MTOT * DM];
__device__ __half h_z [(size_t)MTOT * DM];
__device__ __half h_wq[(size_t)DM * DM];
__device__ __half h_wk[(size_t)DM * DM];
__device__ __half h_wv[(size_t)DM * DM];
__device__ __half h_wo[(size_t)DM * DM];

// ===========================================================================
// helpers
// ===========================================================================
__device__ __forceinline__ void mma_f16(float* d, const unsigned* a, const unsigned* b) {
    asm volatile("mma.sync.aligned.m16n8k16.row.col.f32.f16.f16.f32 "
        "{%0,%1,%2,%3}, {%4,%5,%6,%7}, {%8,%9}, {%0,%1,%2,%3};"
        : "+f"(d[0]), "+f"(d[1]), "+f"(d[2]), "+f"(d[3])
        : "r"(a[0]), "r"(a[1]), "r"(a[2]), "r"(a[3]), "r"(b[0]), "r"(b[1]));
}

__device__ __forceinline__ unsigned pack_h2(float lo, float hi) {
    unsigned r;
    asm("cvt.rn.f16x2.f32 %0, %1, %2;" : "=r"(r) : "f"(hi), "f"(lo));
    return r;
}

__device__ __forceinline__ unsigned smem_u32(const void* p) {
    unsigned r;
    asm("{ .reg .u64 t; cvta.to.shared.u64 t, %1; cvt.u32.u64 %0, t; }"
        : "=r"(r) : "l"(p));
    return r;
}

__device__ __forceinline__ void cp16(unsigned dst, const void* src) {
    asm volatile("cp.async.cg.shared.global [%0], [%1], 16;" :: "r"(dst), "l"(src));
}
#define CP_COMMIT()  asm volatile("cp.async.commit_group;" ::: "memory")
#define CP_WAIT(n)   asm volatile("cp.async.wait_group %0;" :: "n"(n) : "memory")

// ===========================================================================
// prep kernels
// ===========================================================================
// fp32 -> fp16, 16 elems/thread (4 independent float4 loads: MLP=4)
__global__ __launch_bounds__(256) void convx_kernel(
    const float* __restrict__ X, __half* __restrict__ Y)
{
    const size_t i = ((size_t)blockIdx.x * 256 + threadIdx.x) * 16;
    float4 v0 = *(const float4*)&X[i];
    float4 v1 = *(const float4*)&X[i + 4];
    float4 v2 = *(const float4*)&X[i + 8];
    float4 v3 = *(const float4*)&X[i + 12];
    uint4 ua = { pack_h2(v0.x, v0.y), pack_h2(v0.z, v0.w),
                 pack_h2(v1.x, v1.y), pack_h2(v1.z, v1.w) };
    uint4 ub = { pack_h2(v2.x, v2.y), pack_h2(v2.z, v2.w),
                 pack_h2(v3.x, v3.y), pack_h2(v3.z, v3.w) };
    *(uint4*)&Y[i] = ua;
    *(uint4*)&Y[i + 8] = ub;
}

// fused QKV weight transpose+convert: z = mat*16 + head, mat in {Q,K,V}
// W[mat][head][R=1024][C=64] fp32 -> Wt[mat][head*64 + c][R] fp16
__global__ __launch_bounds__(256) void tconv_qkv_kernel(
    const float* __restrict__ WQ, const float* __restrict__ WK,
    const float* __restrict__ WV,
    __half* __restrict__ YQ, __half* __restrict__ YK, __half* __restrict__ YV)
{
    __shared__ float t[32][33];
    const int mat = blockIdx.z >> 4, head = blockIdx.z & 15;
    const float* Xb = ((mat == 0) ? WQ : (mat == 1) ? WK : WV)
                      + (size_t)head * DM * DH;
    __half* Yb = ((mat == 0) ? YQ : (mat == 1) ? YK : YV)
                 + (size_t)head * DH * DM;
    const float scale = (mat == 0) ? 0.125f : 1.f;
    const int r0 = blockIdx.x * 32, c0 = blockIdx.y * 32;
    const int tx = threadIdx.x, ty = threadIdx.y;
    #pragma unroll
    for (int i = ty; i < 32; i += 8)
        t[i][tx] = Xb[(size_t)(r0 + i) * DH + c0 + tx];
    __syncthreads();
    #pragma unroll
    for (int i = ty; i < 32; i += 8)
        Yb[(size_t)(c0 + i) * DM + r0 + tx] = __float2half_rn(t[tx][i] * scale);
}

// single-matrix transpose+convert (W_O [1024][1024])
__global__ __launch_bounds__(256) void tconv_kernel(
    const float* __restrict__ X, __half* __restrict__ Y, int R, int C)
{
    __shared__ float t[32][33];
    const int r0 = blockIdx.x * 32, c0 = blockIdx.y * 32;
    const int tx = threadIdx.x, ty = threadIdx.y;
    #pragma unroll
    for (int i = ty; i < 32; i += 8)
        t[i][tx] = X[(size_t)(r0 + i) * C + c0 + tx];
    __syncthreads();
    #pragma unroll
    for (int i = ty; i < 32; i += 8)
        Y[(size_t)(c0 + i) * R + r0 + tx] = __float2half_rn(t[tx][i]);
}

// ===========================================================================
// fp16 tensor GEMM core (cp.async 3-stage). C = A @ Wt[n][k] + bias*bscale
// ===========================================================================
#define BM 128
#define BN 128
#define KCH 32             // halfs per k-chunk
#define NCHUNK (DM / KCH)  // 32
#define GSTW 20            // row stride in words
#define TOFFW 2560         // words per tile (128*20)
#define GEMM_SMEM 61440

template<int OUTF>
__device__ __forceinline__ void gemm_body(
    const __half* __restrict__ A, const __half* __restrict__ Wt,
    const float* __restrict__ bias, void* __restrict__ Cv, float bscale,
    unsigned* smemw, int m0, int n0)
{
    const unsigned sbase = smem_u32(smemw);
    const int tid = threadIdx.x;
    const int wid = tid >> 5, lane = tid & 31;
    const int g = lane >> 2, tig = lane & 3;
    const int warp_m = wid & 1, warp_n = wid >> 1;

    const int row = tid >> 1;
    const int hc  = (tid & 1) * 16;
    const __half* Aptr = A  + (size_t)(m0 + row) * DM + hc;
    const __half* Bptr = Wt + (size_t)(n0 + row) * DM + hc;
    const unsigned aDst = sbase + (row * GSTW + (tid & 1) * 8) * 4;
    const unsigned bDst = aDst + 3 * TOFFW * 4;

    float acc[4][4][4];
    #pragma unroll
    for (int mt = 0; mt < 4; mt++)
        #pragma unroll
        for (int nt = 0; nt < 4; nt++)
            #pragma unroll
            for (int i = 0; i < 4; i++) acc[mt][nt][i] = 0.f;

    auto stage = [&](int c, int buf) {
        const __half* ap = Aptr + c * KCH;
        const __half* bp = Bptr + c * KCH;
        const unsigned ad = aDst + buf * (TOFFW * 4);
        const unsigned bd = bDst + buf * (TOFFW * 4);
        cp16(ad, ap); cp16(ad + 16, ap + 8);
        cp16(bd, bp); cp16(bd + 16, bp + 8);
    };

    stage(0, 0); CP_COMMIT();
    stage(1, 1); CP_COMMIT();

    int buf = 0;
    for (int c = 0; c < NCHUNK; c++) {
        if (c + 2 < NCHUNK) { stage(c + 2, (c + 2) % 3); CP_COMMIT(); CP_WAIT(2); }
        else if (c + 1 < NCHUNK) { CP_WAIT(1); }
        else { CP_WAIT(0); }
        __syncthreads();

        const unsigned* Asb = smemw + buf * TOFFW;
        const unsigned* Bsb = smemw + 3 * TOFFW + buf * TOFFW;
        #pragma unroll
        for (int kk = 0; kk < 2; kk++) {
            unsigned af[4][4], bf[4][2];
            #pragma unroll
            for (int mt = 0; mt < 4; mt++) {
                const int rb = warp_m * 64 + mt * 16 + g;
                af[mt][0] = Asb[rb * GSTW + kk * 8 + tig];
                af[mt][1] = Asb[(rb + 8) * GSTW + kk * 8 + tig];
                af[mt][2] = Asb[rb * GSTW + kk * 8 + tig + 4];
                af[mt][3] = Asb[(rb + 8) * GSTW + kk * 8 + tig + 4];
            }
            #pragma unroll
            for (int nt = 0; nt < 4; nt++) {
                const int cb = warp_n * 32 + nt * 8 + g;
                bf[nt][0] = Bsb[cb * GSTW + kk * 8 + tig];
                bf[nt][1] = Bsb[cb * GSTW + kk * 8 + tig + 4];
            }
            #pragma unroll
            for (int mt = 0; mt < 4; mt++)
                #pragma unroll
                for (int nt = 0; nt < 4; nt++)
                    mma_f16(acc[mt][nt], af[mt], bf[nt]);
        }
        __syncthreads();
        buf = (buf == 2) ? 0 : buf + 1;
    }

    #pragma unroll
    for (int mt = 0; mt < 4; mt++) {
        const int r0 = m0 + warp_m * 64 + mt * 16 + g;
        #pragma unroll
        for (int nt = 0; nt < 4; nt++) {
            const int col = n0 + warp_n * 32 + nt * 8 + 2 * tig;
            const float bx = bias[col] * bscale, by = bias[col + 1] * bscale;
            if (OUTF) {
                float* C = (float*)Cv;
                float2 v0 = { acc[mt][nt][0] + bx, acc[mt][nt][1] + by };
                float2 v1 = { acc[mt][nt][2] + bx, acc[mt][nt][3] + by };
                *(float2*)&C[(size_t)r0 * DM + col] = v0;
                *(float2*)&C[(size_t)(r0 + 8) * DM + col] = v1;
            } else {
                __half* C = (__half*)Cv;
                *(unsigned*)&C[(size_t)r0 * DM + col] =
                    pack_h2(acc[mt][nt][0] + bx, acc[mt][nt][1] + by);
                *(unsigned*)&C[(size_t)(r0 + 8) * DM + col] =
                    pack_h2(acc[mt][nt][2] + bx, acc[mt][nt][3] + by);
            }
        }
    }
}

// fused QKV: blockIdx.z selects {Q, K, V}
__global__ __launch_bounds__(256, 2) void tc_gemm_qkv(
    const __half* __restrict__ A,
    const __half* __restrict__ W0, const __half* __restrict__ W1,
    const __half* __restrict__ W2,
    const float* __restrict__ b0, const float* __restrict__ b1,
    const float* __restrict__ b2,
    __half* __restrict__ C0, __half* __restrict__ C1, __half* __restrict__ C2)
{
    extern __shared__ __align__(16) unsigned smemw[];
    const int z = blockIdx.z;
    const __half* Wt = (z == 0) ? W0 : (z == 1) ? W1 : W2;
    const float* bias = (z == 0) ? b0 : (z == 1) ? b1 : b2;
    __half* C = (z == 0) ? C0 : (z == 1) ? C1 : C2;
    const float bscale = (z == 0) ? 0.125f : 1.f;
    gemm_body<0>(A, Wt, bias, C, bscale, smemw, blockIdx.y * BM, blockIdx.x * BN);
}

__global__ __launch_bounds__(256, 2) void tc_gemm_out(
    const __half* __restrict__ A, const __half* __restrict__ Wt,
    const float* __restrict__ bias, float* __restrict__ C)
{
    extern __shared__ __align__(16) unsigned smemw[];
    gemm_body<1>(A, Wt, bias, C, 1.f, smemw, blockIdx.y * BM, blockIdx.x * BN);
}

// ===========================================================================
// Flash attention, fp16, m16n8k16, double-buffered K/V pipeline (R11 proven).
// ===========================================================================
#define HST 72   // half stride per row
#define HSW 36   // word stride per row
#define KVBUF (64 * HST)   // halfs per buffer

__global__ __launch_bounds__(256) void flash_h(
    const __half* __restrict__ Q, const __half* __restrict__ K,
    const __half* __restrict__ V, __half* __restrict__ Z)
{
    __shared__ __align__(16) __half ks[2 * KVBUF];
    __shared__ __align__(16) __half vs[2 * KVBUF];
    const unsigned ksb = smem_u32(ks);

    const int tid = threadIdx.x;
    const int wid = tid >> 5, lane = tid & 31;
    const int g = lane >> 2, tig = lane & 3;
    const int qt = gridDim.x - 1 - blockIdx.x;       // heavy tiles first
    const int bh = blockIdx.y;
    const int b = bh >> 4, h = bh & 15;
    const size_t base = ((size_t)b * SEQ * NH + h) * DH;
    const int qrow0 = qt * 128 + wid * 16;

    const int srow = tid >> 2;          // staging row 0..63
    const int sc16 = (tid & 3) * 16;    // half offset within 64-half row
    const unsigned sdst = ksb + srow * 144 + (tid & 3) * 32;

    // ---- Q -> register A-fragments (pre-scaled fp16; 2 cp.async passes) ----
    unsigned aq[4][4];
    #pragma unroll
    for (int pass = 0; pass < 2; pass++) {
        const __half* qp = Q + base + (size_t)(qt * 128 + pass * 64 + srow) * DM + sc16;
        cp16(sdst, qp); cp16(sdst + 16, qp + 8);
        CP_COMMIT(); CP_WAIT(0);
        __syncthreads();
        if ((wid >> 2) == pass) {
            const unsigned* ksw = (const unsigned*)ks;
            const int r = (wid & 3) * 16 + g;
            #pragma unroll
            for (int kk = 0; kk < 4; kk++) {
                aq[kk][0] = ksw[r * HSW + kk * 8 + tig];
                aq[kk][1] = ksw[(r + 8) * HSW + kk * 8 + tig];
                aq[kk][2] = ksw[r * HSW + kk * 8 + tig + 4];
                aq[kk][3] = ksw[(r + 8) * HSW + kk * 8 + tig + 4];
            }
        }
        __syncthreads();
    }

    float m0 = -1e30f, m1 = -1e30f, l0 = 0.f, l1 = 0.f;
    float oacc[8][4];
    #pragma unroll
    for (int nt = 0; nt < 8; nt++)
        #pragma unroll
        for (int i = 0; i < 4; i++) oacc[nt][i] = 0.f;

    const int vkv = tid & 63;          // V staging row
    const int vd0 = (tid >> 6) * 16;   // V staging d group
    const int NKT = 2 * qt + 2;

    // prologue: tile 0 into buf 0
    {
        const __half* kp = K + base + (size_t)srow * DM + sc16;
        cp16(sdst, kp); cp16(sdst + 16, kp + 8);
        CP_COMMIT();
        uint4 v0 = *(const uint4*)&V[base + (size_t)vkv * DM + vd0];
        uint4 v1 = *(const uint4*)&V[base + (size_t)vkv * DM + vd0 + 8];
        const __half* hp0 = (const __half*)&v0;
        const __half* hp1 = (const __half*)&v1;
        #pragma unroll
        for (int j = 0; j < 8; j++) {
            vs[(vd0 + j) * HST + vkv] = hp0[j];
            vs[(vd0 + 8 + j) * HST + vkv] = hp1[j];
        }
        CP_WAIT(0);
        __syncthreads();
    }

    for (int kt = 0; kt < NKT; kt++) {
        const int ktb = kt * 64;
        const int buf = kt & 1, nbuf = buf ^ 1;
        uint4 pv0, pv1;
        const bool pre = (kt + 1 < NKT);
        if (pre) {
            const __half* kp = K + base + (size_t)(ktb + 64 + srow) * DM + sc16;
            const unsigned kd = sdst + nbuf * (KVBUF * 2);
            cp16(kd, kp); cp16(kd + 16, kp + 8);
            CP_COMMIT();
            pv0 = *(const uint4*)&V[base + (size_t)(ktb + 64 + vkv) * DM + vd0];
            pv1 = *(const uint4*)&V[base + (size_t)(ktb + 64 + vkv) * DM + vd0 + 8];
        }

        if (ktb <= qrow0 + 15) {
            const unsigned* ksw = (const unsigned*)(ks + buf * KVBUF);
            const unsigned* vsw = (const unsigned*)(vs + buf * KVBUF);

            // ---- S = Q K^T ----
            float sacc[8][4];
            #pragma unroll
            for (int nt = 0; nt < 8; nt++)
                #pragma unroll
                for (int i = 0; i < 4; i++) sacc[nt][i] = 0.f;

            #pragma unroll
            for (int kk = 0; kk < 4; kk++) {
                unsigned bf[8][2];
                #pragma unroll
                for (int nt = 0; nt < 8; nt++) {
                    bf[nt][0] = ksw[(nt * 8 + g) * HSW + kk * 8 + tig];
                    bf[nt][1] = ksw[(nt * 8 + g) * HSW + kk * 8 + tig + 4];
                }
                #pragma unroll
                for (int nt = 0; nt < 8; nt++)
                    mma_f16(sacc[nt], aq[kk], bf[nt]);
            }

            // ---- causal mask (diagonal tiles only) ----
            if (ktb + 63 > qrow0) {
                #pragma unroll
                for (int nt = 0; nt < 8; nt++) {
                    const int kv0 = ktb + nt * 8 + 2 * tig;
                    if (kv0     > qrow0 + g)     sacc[nt][0] = -1e30f;
                    if (kv0 + 1 > qrow0 + g)     sacc[nt][1] = -1e30f;
                    if (kv0     > qrow0 + g + 8) sacc[nt][2] = -1e30f;
                    if (kv0 + 1 > qrow0 + g + 8) sacc[nt][3] = -1e30f;
                }
            }

            // ---- online softmax ----
            float rm0 = -1e30f, rm1 = -1e30f;
            #pragma unroll
            for (int nt = 0; nt < 8; nt++) {
                rm0 = fmaxf(rm0, fmaxf(sacc[nt][0], sacc[nt][1]));
                rm1 = fmaxf(rm1, fmaxf(sacc[nt][2], sacc[nt][3]));
            }
            rm0 = fmaxf(rm0, __shfl_xor_sync(0xffffffffu, rm0, 1));
            rm0 = fmaxf(rm0, __shfl_xor_sync(0xffffffffu, rm0, 2));
            rm1 = fmaxf(rm1, __shfl_xor_sync(0xffffffffu, rm1, 1));
            rm1 = fmaxf(rm1, __shfl_xor_sync(0xffffffffu, rm1, 2));
            const float mn0 = fmaxf(m0, rm0), mn1 = fmaxf(m1, rm1);
            const float al0 = __expf(m0 - mn0), al1 = __expf(m1 - mn1);
            float rs0 = 0.f, rs1 = 0.f;
            #pragma unroll
            for (int nt = 0; nt < 8; nt++) {
                sacc[nt][0] = __expf(sacc[nt][0] - mn0); rs0 += sacc[nt][0];
                sacc[nt][1] = __expf(sacc[nt][1] - mn0); rs0 += sacc[nt][1];
                sacc[nt][2] = __expf(sacc[nt][2] - mn1); rs1 += sacc[nt][2];
                sacc[nt][3] = __expf(sacc[nt][3] - mn1); rs1 += sacc[nt][3];
            }
            rs0 += __shfl_xor_sync(0xffffffffu, rs0, 1);
            rs0 += __shfl_xor_sync(0xffffffffu, rs0, 2);
            rs1 += __shfl_xor_sync(0xffffffffu, rs1, 1);
            rs1 += __shfl_xor_sync(0xffffffffu, rs1, 2);
            l0 = l0 * al0 + rs0;  l1 = l1 * al1 + rs1;
            m0 = mn0;             m1 = mn1;
            #pragma unroll
            for (int nt = 0; nt < 8; nt++) {
                oacc[nt][0] *= al0; oacc[nt][1] *= al0;
                oacc[nt][2] *= al1; oacc[nt][3] *= al1;
            }

            // ---- O += P V : S C-fragment IS the A-fragment ----
            #pragma unroll
            for (int kk = 0; kk < 4; kk++) {
                unsigned ap[4];
                ap[0] = pack_h2(sacc[2*kk][0],   sacc[2*kk][1]);
                ap[1] = pack_h2(sacc[2*kk][2],   sacc[2*kk][3]);
                ap[2] = pack_h2(sacc[2*kk+1][0], sacc[2*kk+1][1]);
                ap[3] = pack_h2(sacc[2*kk+1][2], sacc[2*kk+1][3]);
                unsigned bf[8][2];
                #pragma unroll
                for (int nt = 0; nt < 8; nt++) {
                    bf[nt][0] = vsw[(nt * 8 + g) * HSW + kk * 8 + tig];
                    bf[nt][1] = vsw[(nt * 8 + g) * HSW + kk * 8 + tig + 4];
                }
                #pragma unroll
                for (int nt = 0; nt < 8; nt++)
                    mma_f16(oacc[nt], ap, bf[nt]);
            }
        }

        if (pre) {
            __half* vb = vs + nbuf * KVBUF;
            const __half* hp0 = (const __half*)&pv0;
            const __half* hp1 = (const __half*)&pv1;
            #pragma unroll
            for (int j = 0; j < 8; j++) {
                vb[(vd0 + j) * HST + vkv] = hp0[j];
                vb[(vd0 + 8 + j) * HST + vkv] = hp1[j];
            }
            CP_WAIT(0);
        }
        __syncthreads();
    }

    // ---- normalize + write z (fp16) ----
    const float i0 = 1.f / l0, i1 = 1.f / l1;
    #pragma unroll
    for (int nt = 0; nt < 8; nt++) {
        const int col = nt * 8 + 2 * tig;
        const int row = qrow0 + g;
        *(unsigned*)&Z[base + (size_t)row * DM + col] =
            pack_h2(oacc[nt][0] * i0, oacc[nt][1] * i0);
        *(unsigned*)&Z[base + (size_t)(row + 8) * DM + col] =
            pack_h2(oacc[nt][2] * i1, oacc[nt][3] * i1);
    }
}

// ---------------------------------------------------------------------------

extern "C" void kernel_launch(void* const* d_in, const int* in_sizes, int n_in,
                              void* d_out, int out_size)
{
    const float* x  = (const float*)d_in[0];
    const float* WQ = (const float*)d_in[1];
    const float* WK = (const float*)d_in[2];
    const float* WV = (const float*)d_in[3];
    const float* WO = (const float*)d_in[4];
    const float* bQ = (const float*)d_in[5];
    const float* bK = (const float*)d_in[6];
    const float* bV = (const float*)d_in[7];
    const float* bO = (const float*)d_in[8];
    float* out = (float*)d_out;

    __half *xh, *qh, *kh, *vh, *zh, *wqt, *wkt, *wvt, *wot;
    cudaGetSymbolAddress((void**)&xh,  h_x);
    cudaGetSymbolAddress((void**)&qh,  h_q);
    cudaGetSymbolAddress((void**)&kh,  h_k);
    cudaGetSymbolAddress((void**)&vh,  h_v);
    cudaGetSymbolAddress((void**)&zh,  h_z);
    cudaGetSymbolAddress((void**)&wqt, h_wq);
    cudaGetSymbolAddress((void**)&wkt, h_wk);
    cudaGetSymbolAddress((void**)&wvt, h_wv);
    cudaGetSymbolAddress((void**)&wot, h_wo);

    cudaFuncSetAttribute(tc_gemm_qkv, cudaFuncAttributeMaxDynamicSharedMemorySize, GEMM_SMEM);
    cudaFuncSetAttribute(tc_gemm_out, cudaFuncAttributeMaxDynamicSharedMemorySize, GEMM_SMEM);

    // prep: convert x (MLP=4); fused QKV weight transpose; WO transpose
    convx_kernel<<<(MTOT * DM) / 4096, 256>>>(x, xh);
    tconv_qkv_kernel<<<dim3(32, 2, 48), dim3(32, 8)>>>(WQ, WK, WV, wqt, wkt, wvt);
    tconv_kernel<<<dim3(32, 32, 1), dim3(32, 8)>>>(WO, wot, DM, DM);

    tc_gemm_qkv<<<dim3(DM / BN, MTOT / BM, 3), 256, GEMM_SMEM>>>(
        xh, wqt, wkt, wvt, bQ, bK, bV, qh, kh, vh);
    flash_h<<<dim3(SEQ / 128, BATCH * NH), 256>>>(qh, kh, vh, zh);
    tc_gemm_out<<<dim3(DM / BN, MTOT / BM), 256, GEMM_SMEM>>>(zh, wot, bO, out);
}